// round 2
// baseline (speedup 1.0000x reference)
#include <cuda_runtime.h>
#include <cuda_bf16.h>
#include <math.h>

#define B_ 4
#define H_ 8
#define N_ 1024
#define D_ 64
#define C_ 512
#define M_ 4096   // B_*N_

// Scratch (no allocation allowed) — 5 x 8MB fp32
__device__ float g_q[M_ * C_];
__device__ float g_k[M_ * C_];
__device__ float g_v[M_ * C_];
__device__ float g_gate[M_ * C_];
__device__ float g_o[M_ * C_];

// ---------------------------------------------------------------------------
// GEMM: C[m][o] = epilogue( sum_k A[m][k] * W[o][k] )
// A: [4096, 512] row-major, W: [512, 512] row-major (output-feature rows)
// mode 0: (x + b1[o]) * 0.125f            (q projection, pre-scaled)
// mode 1: x                               (k / v projections)
// mode 3: sigmoid(x + b1[o] + b2[o])      (gate)
// mode 4: (x + b1[o]) * gate[m][o]        (final output projection)
// ---------------------------------------------------------------------------
__global__ __launch_bounds__(256) void proj_kernel(
    const float* __restrict__ A, const float* __restrict__ W,
    const float* __restrict__ b1, const float* __restrict__ b2,
    const float* __restrict__ gate, float* __restrict__ C, int mode)
{
    __shared__ float As[64][17];
    __shared__ float Ws[64][17];

    const int tid = threadIdx.x;
    const int ty = tid >> 4;          // 0..15
    const int tx = tid & 15;          // 0..15
    const int m0 = blockIdx.x << 6;
    const int o0 = blockIdx.y << 6;
    const int lr = tid >> 2;          // 0..63
    const int lc = (tid & 3) << 2;    // 0,4,8,12

    float acc[4][4] = {};

    const float* Ap = A + (size_t)(m0 + lr) * C_ + lc;
    const float* Wp = W + (size_t)(o0 + lr) * C_ + lc;

    for (int k0 = 0; k0 < C_; k0 += 16) {
        float4 va = *(const float4*)(Ap + k0);
        float4 vw = *(const float4*)(Wp + k0);
        As[lr][lc + 0] = va.x; As[lr][lc + 1] = va.y;
        As[lr][lc + 2] = va.z; As[lr][lc + 3] = va.w;
        Ws[lr][lc + 0] = vw.x; Ws[lr][lc + 1] = vw.y;
        Ws[lr][lc + 2] = vw.z; Ws[lr][lc + 3] = vw.w;
        __syncthreads();
#pragma unroll
        for (int kk = 0; kk < 16; kk++) {
            float a[4], b[4];
#pragma unroll
            for (int i = 0; i < 4; i++) a[i] = As[4 * ty + i][kk];
#pragma unroll
            for (int j = 0; j < 4; j++) b[j] = Ws[4 * tx + j][kk];
#pragma unroll
            for (int i = 0; i < 4; i++)
#pragma unroll
                for (int j = 0; j < 4; j++)
                    acc[i][j] = fmaf(a[i], b[j], acc[i][j]);
        }
        __syncthreads();
    }

    const int oc = o0 + 4 * tx;
#pragma unroll
    for (int i = 0; i < 4; i++) {
        const int m = m0 + 4 * ty + i;
        float r0 = acc[i][0], r1 = acc[i][1], r2 = acc[i][2], r3 = acc[i][3];
        if (mode == 0) {
            float4 bb = *(const float4*)(b1 + oc);
            r0 = (r0 + bb.x) * 0.125f; r1 = (r1 + bb.y) * 0.125f;
            r2 = (r2 + bb.z) * 0.125f; r3 = (r3 + bb.w) * 0.125f;
        } else if (mode == 3) {
            float4 bb = *(const float4*)(b1 + oc);
            float4 gb = *(const float4*)(b2 + oc);
            r0 = 1.f / (1.f + __expf(-(r0 + bb.x + gb.x)));
            r1 = 1.f / (1.f + __expf(-(r1 + bb.y + gb.y)));
            r2 = 1.f / (1.f + __expf(-(r2 + bb.z + gb.z)));
            r3 = 1.f / (1.f + __expf(-(r3 + bb.w + gb.w)));
        } else if (mode == 4) {
            float4 bb = *(const float4*)(b1 + oc);
            float4 gg = *(const float4*)(gate + (size_t)m * C_ + oc);
            r0 = (r0 + bb.x) * gg.x; r1 = (r1 + bb.y) * gg.y;
            r2 = (r2 + bb.z) * gg.z; r3 = (r3 + bb.w) * gg.w;
        }
        float4 o4 = make_float4(r0, r1, r2, r3);
        *(float4*)(C + (size_t)m * C_ + oc) = o4;
    }
}

// ---------------------------------------------------------------------------
// Flash attention with additive bias.
// Q,K,V: [B*N, C] layout where head h occupies columns [h*64, h*64+64).
// Grid: (N/64, B*H). Block: 256 threads; each thread owns a 4x4 microtile.
// Online softmax state kept in registers, row reductions via 16-lane shuffles.
// ---------------------------------------------------------------------------
__global__ __launch_bounds__(256) void attn_kernel(
    const float* __restrict__ Q, const float* __restrict__ K,
    const float* __restrict__ V, const float* __restrict__ bias,
    float* __restrict__ O)
{
    extern __shared__ float sm[];
    float* Qs = sm;                 // [64][65]
    float* KP = sm + 64 * 65;       // [64][65]  K tile, later reused as P tile
    float* Vs = sm + 2 * 64 * 65;   // [64][65]

    const int tid = threadIdx.x;
    const int ty = tid >> 4;
    const int tx = tid & 15;
    const int bh = blockIdx.y;
    const int b = bh >> 3, h = bh & 7;
    const int q0 = blockIdx.x << 6;

    const float* Qb = Q + (size_t)b * N_ * C_ + h * D_;
    const float* Kb = K + (size_t)b * N_ * C_ + h * D_;
    const float* Vb = V + (size_t)b * N_ * C_ + h * D_;
    const float* Biasb = bias + (size_t)bh * N_ * N_;

    // Load Q tile (64 rows x 64 cols)
#pragma unroll
    for (int it = 0; it < 4; it++) {
        int idx = tid + (it << 8);
        int r = idx >> 4;
        int c = (idx & 15) << 2;
        float4 v4 = *(const float4*)(Qb + (size_t)(q0 + r) * C_ + c);
        float* dst = Qs + r * 65 + c;
        dst[0] = v4.x; dst[1] = v4.y; dst[2] = v4.z; dst[3] = v4.w;
    }

    float mrow[4], lrow[4], oa[4][4];
#pragma unroll
    for (int i = 0; i < 4; i++) {
        mrow[i] = -1e30f; lrow[i] = 0.f;
#pragma unroll
        for (int j = 0; j < 4; j++) oa[i][j] = 0.f;
    }
    __syncthreads();

    for (int kt = 0; kt < 16; kt++) {
        const int k0 = kt << 6;
        // Load K tile and V tile
#pragma unroll
        for (int it = 0; it < 4; it++) {
            int idx = tid + (it << 8);
            int r = idx >> 4;
            int c = (idx & 15) << 2;
            float4 kv = *(const float4*)(Kb + (size_t)(k0 + r) * C_ + c);
            float4 vv = *(const float4*)(Vb + (size_t)(k0 + r) * C_ + c);
            float* kd = KP + r * 65 + c;
            kd[0] = kv.x; kd[1] = kv.y; kd[2] = kv.z; kd[3] = kv.w;
            float* vd = Vs + r * 65 + c;
            vd[0] = vv.x; vd[1] = vv.y; vd[2] = vv.z; vd[3] = vv.w;
        }
        __syncthreads();

        // S = Q @ K^T
        float s[4][4] = {};
#pragma unroll 16
        for (int kk = 0; kk < 64; kk++) {
            float a[4], bb[4];
#pragma unroll
            for (int i = 0; i < 4; i++) a[i] = Qs[(4 * ty + i) * 65 + kk];
#pragma unroll
            for (int j = 0; j < 4; j++) bb[j] = KP[(4 * tx + j) * 65 + kk];
#pragma unroll
            for (int i = 0; i < 4; i++)
#pragma unroll
                for (int j = 0; j < 4; j++)
                    s[i][j] = fmaf(a[i], bb[j], s[i][j]);
        }

        // S += bias
#pragma unroll
        for (int i = 0; i < 4; i++) {
            float4 bv = *(const float4*)(Biasb + (size_t)(q0 + 4 * ty + i) * N_ + k0 + 4 * tx);
            s[i][0] += bv.x; s[i][1] += bv.y; s[i][2] += bv.z; s[i][3] += bv.w;
        }

        // Online softmax (row reductions across the 16 tx lanes)
#pragma unroll
        for (int i = 0; i < 4; i++) {
            float mt = fmaxf(fmaxf(s[i][0], s[i][1]), fmaxf(s[i][2], s[i][3]));
#pragma unroll
            for (int sh = 8; sh >= 1; sh >>= 1)
                mt = fmaxf(mt, __shfl_xor_sync(0xffffffffu, mt, sh));
            float mn = fmaxf(mrow[i], mt);
            float alpha = __expf(mrow[i] - mn);
            mrow[i] = mn;
            float rs = 0.f;
#pragma unroll
            for (int j = 0; j < 4; j++) { s[i][j] = __expf(s[i][j] - mn); rs += s[i][j]; }
#pragma unroll
            for (int sh = 8; sh >= 1; sh >>= 1)
                rs += __shfl_xor_sync(0xffffffffu, rs, sh);
            lrow[i] = lrow[i] * alpha + rs;
#pragma unroll
            for (int j = 0; j < 4; j++) oa[i][j] *= alpha;
        }
        __syncthreads();   // everyone done reading K from KP

        // Stage P through smem (reuses K tile storage)
#pragma unroll
        for (int i = 0; i < 4; i++)
#pragma unroll
            for (int j = 0; j < 4; j++)
                KP[(4 * ty + i) * 65 + 4 * tx + j] = s[i][j];
        __syncthreads();

        // O += P @ V
#pragma unroll 16
        for (int kk = 0; kk < 64; kk++) {
            float a[4], bb[4];
#pragma unroll
            for (int i = 0; i < 4; i++) a[i] = KP[(4 * ty + i) * 65 + kk];
#pragma unroll
            for (int j = 0; j < 4; j++) bb[j] = Vs[kk * 65 + 4 * tx + j];
#pragma unroll
            for (int i = 0; i < 4; i++)
#pragma unroll
                for (int j = 0; j < 4; j++)
                    oa[i][j] = fmaf(a[i], bb[j], oa[i][j]);
        }
        __syncthreads();   // before next tile overwrites KP/Vs
    }

    // Normalize and store O in [B*N, C] layout (head h columns)
#pragma unroll
    for (int i = 0; i < 4; i++) {
        float inv = 1.f / lrow[i];
        float4 o4 = make_float4(oa[i][0] * inv, oa[i][1] * inv,
                                oa[i][2] * inv, oa[i][3] * inv);
        *(float4*)(O + (size_t)(b * N_ + q0 + 4 * ty + i) * C_ + h * D_ + 4 * tx) = o4;
    }
}

// ---------------------------------------------------------------------------
extern "C" void kernel_launch(void* const* d_in, const int* in_sizes, int n_in,
                              void* d_out, int out_size)
{
    const float* q_x   = (const float*)d_in[0];
    const float* bias  = (const float*)d_in[1];
    const float* Wq    = (const float*)d_in[2];
    const float* bq    = (const float*)d_in[3];
    const float* Wk    = (const float*)d_in[4];
    const float* Wv    = (const float*)d_in[5];
    const float* Wo    = (const float*)d_in[6];
    const float* bo    = (const float*)d_in[7];
    const float* Wg    = (const float*)d_in[8];
    const float* bg    = (const float*)d_in[9];
    const float* gbias = (const float*)d_in[10];
    float* out = (float*)d_out;

    float *pq, *pk, *pv, *pg, *po;
    cudaGetSymbolAddress((void**)&pq, g_q);
    cudaGetSymbolAddress((void**)&pk, g_k);
    cudaGetSymbolAddress((void**)&pv, g_v);
    cudaGetSymbolAddress((void**)&pg, g_gate);
    cudaGetSymbolAddress((void**)&po, g_o);

    const int attn_smem = 3 * 64 * 65 * 4;  // 49920 bytes
    cudaFuncSetAttribute(attn_kernel, cudaFuncAttributeMaxDynamicSharedMemorySize,
                         attn_smem);

    dim3 pgrid(M_ / 64, C_ / 64);   // (64, 8)
    proj_kernel<<<pgrid, 256>>>(q_x, Wq, bq, nullptr, nullptr, pq, 0);
    proj_kernel<<<pgrid, 256>>>(q_x, Wk, nullptr, nullptr, nullptr, pk, 1);
    proj_kernel<<<pgrid, 256>>>(q_x, Wv, nullptr, nullptr, nullptr, pv, 1);
    proj_kernel<<<pgrid, 256>>>(q_x, Wg, bg, gbias, nullptr, pg, 3);

    dim3 agrid(N_ / 64, B_ * H_);   // (16, 32)
    attn_kernel<<<agrid, 256, attn_smem>>>(pq, pk, pv, bias, po);

    proj_kernel<<<pgrid, 256>>>(po, Wo, bo, nullptr, pg, out, 4);
}

// round 5
// speedup vs baseline: 1.6525x; 1.6525x over previous
#include <cuda_runtime.h>
#include <cuda_bf16.h>
#include <math.h>
#include <cstdint>

#define B_ 4
#define H_ 8
#define N_ 1024
#define D_ 64
#define C_ 512
#define M_ 4096   // B_*N_

// ---------------- scratch (no allocation allowed) ----------------
__device__ float g_q[M_ * C_];
__device__ float g_k[M_ * C_];
__device__ float g_v[M_ * C_];
__device__ float g_gate[M_ * C_];
__device__ float g_o[M_ * C_];
__device__ __nv_bfloat16 g_ahi[M_ * C_];
__device__ __nv_bfloat16 g_alo[M_ * C_];
__device__ __nv_bfloat16 g_whi[5 * C_ * C_];
__device__ __nv_bfloat16 g_wlo[5 * C_ * C_];

// ---------------- helpers (plain sm_103-safe PTX only) ----------------
__device__ __forceinline__ uint32_t smem_u32(const void* p) {
    uint32_t a;
    asm("{ .reg .u64 t; cvta.to.shared.u64 t, %1; cvt.u32.u64 %0, t; }"
        : "=r"(a) : "l"(p));
    return a;
}
#define SW128(o) ((o) ^ (((o) >> 3) & 0x70))

#define CP_ASYNC16(dst, src) \
    asm volatile("cp.async.cg.shared.global [%0], [%1], 16;" \
                 :: "r"(dst), "l"(src) : "memory")
#define CP_COMMIT() asm volatile("cp.async.commit_group;" ::: "memory")
#define CP_WAIT0()  asm volatile("cp.async.wait_group 0;" ::: "memory")
#define CP_WAIT1()  asm volatile("cp.async.wait_group 1;" ::: "memory")

#define LDSM_X4(r, addr) \
    asm volatile("ldmatrix.sync.aligned.m8n8.x4.shared.b16 {%0,%1,%2,%3}, [%4];" \
                 : "=r"((r)[0]), "=r"((r)[1]), "=r"((r)[2]), "=r"((r)[3]) : "r"(addr))

__device__ __forceinline__ void mma16816(float* d, const uint32_t* a, const uint32_t* b) {
    asm volatile(
        "mma.sync.aligned.m16n8k16.row.col.f32.bf16.bf16.f32 "
        "{%0,%1,%2,%3}, {%4,%5,%6,%7}, {%8,%9}, {%0,%1,%2,%3};"
        : "+f"(d[0]), "+f"(d[1]), "+f"(d[2]), "+f"(d[3])
        : "r"(a[0]), "r"(a[1]), "r"(a[2]), "r"(a[3]), "r"(b[0]), "r"(b[1]));
}

// ---------------- fp32 -> (hi, lo) bf16 split ----------------
__global__ __launch_bounds__(256) void split_kernel(
    const float* __restrict__ x, __nv_bfloat16* __restrict__ hi,
    __nv_bfloat16* __restrict__ lo, int n)
{
    int i = (blockIdx.x * 256 + threadIdx.x) * 4;
    if (i >= n) return;
    float4 v = *(const float4*)(x + i);
    float a0 = v.x, a1 = v.y, a2 = v.z, a3 = v.w;
    __nv_bfloat16 h0 = __float2bfloat16(a0), h1 = __float2bfloat16(a1);
    __nv_bfloat16 h2 = __float2bfloat16(a2), h3 = __float2bfloat16(a3);
    __nv_bfloat16 l0 = __float2bfloat16(a0 - __bfloat162float(h0));
    __nv_bfloat16 l1 = __float2bfloat16(a1 - __bfloat162float(h1));
    __nv_bfloat16 l2 = __float2bfloat16(a2 - __bfloat162float(h2));
    __nv_bfloat16 l3 = __float2bfloat16(a3 - __bfloat162float(h3));
    ((__nv_bfloat162*)(hi + i))[0] = __halves2bfloat162(h0, h1);
    ((__nv_bfloat162*)(hi + i))[1] = __halves2bfloat162(h2, h3);
    ((__nv_bfloat162*)(lo + i))[0] = __halves2bfloat162(l0, l1);
    ((__nv_bfloat162*)(lo + i))[1] = __halves2bfloat162(l2, l3);
}

// ---------------- mma.sync projection GEMM ----------------
// C[m][o] = epi( sum_k A[m][k] * W[o][k] ), bf16 3-term split, fp32 accum.
// Tile 128x128, K-chunk 64, double-buffered cp.async, SW128 smem + ldmatrix.
// z: 0=q (x+bq)*0.125 ; 1=k ; 2=v ; 3=sigmoid(x+bg+gbias) ; 4=(x+bo)*gate
#define TS 16384                   // one tile: 128 rows x 128 bytes
#define PROJ_SMEM (8 * TS)         // 131072: 2 buffers x 4 tiles

__global__ __launch_bounds__(256, 1) void mma_proj(
    const __nv_bfloat16* __restrict__ Ahi, const __nv_bfloat16* __restrict__ Alo,
    const __nv_bfloat16* __restrict__ Whi_base, const __nv_bfloat16* __restrict__ Wlo_base,
    const float* __restrict__ bq, const float* __restrict__ bg,
    const float* __restrict__ gbias, const float* __restrict__ bo,
    const float* __restrict__ gate,
    float* __restrict__ outq, float* __restrict__ outk,
    float* __restrict__ outv, float* __restrict__ outg, float* __restrict__ outo,
    int final_pass)
{
    extern __shared__ char smem[];
    const uint32_t sb = smem_u32(smem);
    const int tid = threadIdx.x;
    const int lane = tid & 31;
    const int wid = tid >> 5;
    const int wm = wid & 3;        // 0..3 -> m offset wm*32
    const int wn = wid >> 2;       // 0..1 -> n offset wn*64
    const int m0 = blockIdx.x * 128;
    const int o0 = blockIdx.y * 128;
    const int z = final_pass ? 4 : (int)blockIdx.z;

    const __nv_bfloat16* Whi = Whi_base + (size_t)z * C_ * C_;
    const __nv_bfloat16* Wlo = Wlo_base + (size_t)z * C_ * C_;

    float acc[2][8][4];
#pragma unroll
    for (int i = 0; i < 2; i++)
#pragma unroll
        for (int j = 0; j < 8; j++)
#pragma unroll
            for (int c = 0; c < 4; c++) acc[i][j][c] = 0.f;

    // ---- async load of one K-chunk (4 tiles) into buffer ----
    auto issue = [&](int ic) {
        const int buf = ic & 1;
        const uint32_t db = sb + buf * 4 * TS;
        const int k0 = ic * 64;
#pragma unroll
        for (int it = 0; it < 4; it++) {
            int seg = it * 256 + tid;         // 0..1023
            int r = seg >> 3;                 // 0..127
            int c16 = seg & 7;                // 0..7
            uint32_t sw = SW128((uint32_t)(r * 128 + c16 * 16));
            size_t aoff = (size_t)(m0 + r) * C_ + k0 + c16 * 8;
            size_t woff = (size_t)(o0 + r) * C_ + k0 + c16 * 8;
            CP_ASYNC16(db + 0 * TS + sw, Ahi + aoff);
            CP_ASYNC16(db + 1 * TS + sw, Alo + aoff);
            CP_ASYNC16(db + 2 * TS + sw, Whi + woff);
            CP_ASYNC16(db + 3 * TS + sw, Wlo + woff);
        }
        CP_COMMIT();
    };

    // fragment address components (constant across chunks)
    const int a_row = wm * 32 + (lane & 15);
    const int a_kc0 = (lane >> 4) * 8;                       // k half
    const int b_n   = wn * 64 + (lane & 7) + (lane >> 4) * 8; // n row in W tile
    const int b_kc0 = ((lane >> 3) & 1) * 8;

    auto compute = [&](int buf) {
        const uint32_t tb = sb + buf * 4 * TS;
#pragma unroll
        for (int ks = 0; ks < 4; ks++) {
            uint32_t ah[2][4], al[2][4], bf[4][4];
            const int akc = ks * 16 + a_kc0;
            const int bkc = ks * 16 + b_kc0;
#pragma unroll
            for (int mi = 0; mi < 2; mi++) {
                uint32_t off = (uint32_t)((a_row + mi * 16) * 128 + akc * 2);
                LDSM_X4(ah[mi], tb + 0 * TS + SW128(off));
                LDSM_X4(al[mi], tb + 1 * TS + SW128(off));
            }
#pragma unroll
            for (int p = 0; p < 4; p++) {
                uint32_t off = (uint32_t)((b_n + p * 16) * 128 + bkc * 2);
                LDSM_X4(bf[p], tb + 2 * TS + SW128(off));   // Whi
            }
            // Ahi*Whi + Alo*Whi
#pragma unroll
            for (int mi = 0; mi < 2; mi++)
#pragma unroll
                for (int p = 0; p < 4; p++) {
                    mma16816(acc[mi][2 * p + 0], ah[mi], &bf[p][0]);
                    mma16816(acc[mi][2 * p + 1], ah[mi], &bf[p][2]);
                    mma16816(acc[mi][2 * p + 0], al[mi], &bf[p][0]);
                    mma16816(acc[mi][2 * p + 1], al[mi], &bf[p][2]);
                }
            // reload Wlo over bf, Ahi*Wlo
#pragma unroll
            for (int p = 0; p < 4; p++) {
                uint32_t off = (uint32_t)((b_n + p * 16) * 128 + bkc * 2);
                LDSM_X4(bf[p], tb + 3 * TS + SW128(off));   // Wlo
            }
#pragma unroll
            for (int mi = 0; mi < 2; mi++)
#pragma unroll
                for (int p = 0; p < 4; p++) {
                    mma16816(acc[mi][2 * p + 0], ah[mi], &bf[p][0]);
                    mma16816(acc[mi][2 * p + 1], ah[mi], &bf[p][2]);
                }
        }
    };

    issue(0);
    for (int ic = 0; ic < 8; ic++) {
        if (ic < 7) { issue(ic + 1); CP_WAIT1(); }
        else        { CP_WAIT0(); }
        __syncthreads();
        compute(ic & 1);
        __syncthreads();
    }

    // ---- epilogue ----
    float* out = (z == 0) ? outq : (z == 1) ? outk : (z == 2) ? outv
               : (z == 3) ? outg : outo;

    auto store2 = [&](int m, int c, float v0, float v1) {
        if (z == 0) {
            v0 = (v0 + bq[c]) * 0.125f;
            v1 = (v1 + bq[c + 1]) * 0.125f;
        } else if (z == 3) {
            v0 = 1.f / (1.f + __expf(-(v0 + bg[c] + gbias[c])));
            v1 = 1.f / (1.f + __expf(-(v1 + bg[c + 1] + gbias[c + 1])));
        } else if (z == 4) {
            v0 = (v0 + bo[c]) * gate[(size_t)m * C_ + c];
            v1 = (v1 + bo[c + 1]) * gate[(size_t)m * C_ + c + 1];
        }
        float2 o2 = make_float2(v0, v1);
        *(float2*)(out + (size_t)m * C_ + c) = o2;
    };

#pragma unroll
    for (int mi = 0; mi < 2; mi++)
#pragma unroll
        for (int nj = 0; nj < 8; nj++) {
            int row = m0 + wm * 32 + mi * 16 + (lane >> 2);
            int col = o0 + wn * 64 + nj * 8 + (lane & 3) * 2;
            store2(row,     col, acc[mi][nj][0], acc[mi][nj][1]);
            store2(row + 8, col, acc[mi][nj][2], acc[mi][nj][3]);
        }
}

// ---------------------------------------------------------------------------
// Flash attention with additive bias (SIMT fp32), known-correct from R1.
// ---------------------------------------------------------------------------
__global__ __launch_bounds__(256) void attn_kernel(
    const float* __restrict__ Q, const float* __restrict__ K,
    const float* __restrict__ V, const float* __restrict__ bias,
    float* __restrict__ O)
{
    extern __shared__ float sm[];
    float* Qs = sm;
    float* KP = sm + 64 * 65;
    float* Vs = sm + 2 * 64 * 65;

    const int tid = threadIdx.x;
    const int ty = tid >> 4;
    const int tx = tid & 15;
    const int bh = blockIdx.y;
    const int b = bh >> 3, h = bh & 7;
    const int q0 = blockIdx.x << 6;

    const float* Qb = Q + (size_t)b * N_ * C_ + h * D_;
    const float* Kb = K + (size_t)b * N_ * C_ + h * D_;
    const float* Vb = V + (size_t)b * N_ * C_ + h * D_;
    const float* Biasb = bias + (size_t)bh * N_ * N_;

#pragma unroll
    for (int it = 0; it < 4; it++) {
        int idx = tid + (it << 8);
        int r = idx >> 4;
        int c = (idx & 15) << 2;
        float4 v4 = *(const float4*)(Qb + (size_t)(q0 + r) * C_ + c);
        float* dst = Qs + r * 65 + c;
        dst[0] = v4.x; dst[1] = v4.y; dst[2] = v4.z; dst[3] = v4.w;
    }

    float mrow[4], lrow[4], oa[4][4];
#pragma unroll
    for (int i = 0; i < 4; i++) {
        mrow[i] = -1e30f; lrow[i] = 0.f;
#pragma unroll
        for (int j = 0; j < 4; j++) oa[i][j] = 0.f;
    }
    __syncthreads();

    for (int kt = 0; kt < 16; kt++) {
        const int k0 = kt << 6;
#pragma unroll
        for (int it = 0; it < 4; it++) {
            int idx = tid + (it << 8);
            int r = idx >> 4;
            int c = (idx & 15) << 2;
            float4 kv = *(const float4*)(Kb + (size_t)(k0 + r) * C_ + c);
            float4 vv = *(const float4*)(Vb + (size_t)(k0 + r) * C_ + c);
            float* kd = KP + r * 65 + c;
            kd[0] = kv.x; kd[1] = kv.y; kd[2] = kv.z; kd[3] = kv.w;
            float* vd = Vs + r * 65 + c;
            vd[0] = vv.x; vd[1] = vv.y; vd[2] = vv.z; vd[3] = vv.w;
        }
        __syncthreads();

        float s[4][4] = {};
#pragma unroll 16
        for (int kk = 0; kk < 64; kk++) {
            float a[4], bb[4];
#pragma unroll
            for (int i = 0; i < 4; i++) a[i] = Qs[(4 * ty + i) * 65 + kk];
#pragma unroll
            for (int j = 0; j < 4; j++) bb[j] = KP[(4 * tx + j) * 65 + kk];
#pragma unroll
            for (int i = 0; i < 4; i++)
#pragma unroll
                for (int j = 0; j < 4; j++)
                    s[i][j] = fmaf(a[i], bb[j], s[i][j]);
        }

#pragma unroll
        for (int i = 0; i < 4; i++) {
            float4 bv = *(const float4*)(Biasb + (size_t)(q0 + 4 * ty + i) * N_ + k0 + 4 * tx);
            s[i][0] += bv.x; s[i][1] += bv.y; s[i][2] += bv.z; s[i][3] += bv.w;
        }

#pragma unroll
        for (int i = 0; i < 4; i++) {
            float mt = fmaxf(fmaxf(s[i][0], s[i][1]), fmaxf(s[i][2], s[i][3]));
#pragma unroll
            for (int sh = 8; sh >= 1; sh >>= 1)
                mt = fmaxf(mt, __shfl_xor_sync(0xffffffffu, mt, sh));
            float mn = fmaxf(mrow[i], mt);
            float alpha = __expf(mrow[i] - mn);
            mrow[i] = mn;
            float rs = 0.f;
#pragma unroll
            for (int j = 0; j < 4; j++) { s[i][j] = __expf(s[i][j] - mn); rs += s[i][j]; }
#pragma unroll
            for (int sh = 8; sh >= 1; sh >>= 1)
                rs += __shfl_xor_sync(0xffffffffu, rs, sh);
            lrow[i] = lrow[i] * alpha + rs;
#pragma unroll
            for (int j = 0; j < 4; j++) oa[i][j] *= alpha;
        }
        __syncthreads();

#pragma unroll
        for (int i = 0; i < 4; i++)
#pragma unroll
            for (int j = 0; j < 4; j++)
                KP[(4 * ty + i) * 65 + 4 * tx + j] = s[i][j];
        __syncthreads();

#pragma unroll 16
        for (int kk = 0; kk < 64; kk++) {
            float a[4], bb[4];
#pragma unroll
            for (int i = 0; i < 4; i++) a[i] = KP[(4 * ty + i) * 65 + kk];
#pragma unroll
            for (int j = 0; j < 4; j++) bb[j] = Vs[kk * 65 + 4 * tx + j];
#pragma unroll
            for (int i = 0; i < 4; i++)
#pragma unroll
                for (int j = 0; j < 4; j++)
                    oa[i][j] = fmaf(a[i], bb[j], oa[i][j]);
        }
        __syncthreads();
    }

#pragma unroll
    for (int i = 0; i < 4; i++) {
        float inv = 1.f / lrow[i];
        float4 o4 = make_float4(oa[i][0] * inv, oa[i][1] * inv,
                                oa[i][2] * inv, oa[i][3] * inv);
        *(float4*)(O + (size_t)(b * N_ + q0 + 4 * ty + i) * C_ + h * D_ + 4 * tx) = o4;
    }
}

// ---------------------------------------------------------------------------
extern "C" void kernel_launch(void* const* d_in, const int* in_sizes, int n_in,
                              void* d_out, int out_size)
{
    const float* q_x   = (const float*)d_in[0];
    const float* bias  = (const float*)d_in[1];
    const float* Wq    = (const float*)d_in[2];
    const float* bq    = (const float*)d_in[3];
    const float* Wk    = (const float*)d_in[4];
    const float* Wv    = (const float*)d_in[5];
    const float* Wo    = (const float*)d_in[6];
    const float* bo    = (const float*)d_in[7];
    const float* Wg    = (const float*)d_in[8];
    const float* bg    = (const float*)d_in[9];
    const float* gbias = (const float*)d_in[10];
    float* out = (float*)d_out;

    float *pq, *pk, *pv, *pg, *po;
    __nv_bfloat16 *ahi, *alo, *whi, *wlo;
    cudaGetSymbolAddress((void**)&pq, g_q);
    cudaGetSymbolAddress((void**)&pk, g_k);
    cudaGetSymbolAddress((void**)&pv, g_v);
    cudaGetSymbolAddress((void**)&pg, g_gate);
    cudaGetSymbolAddress((void**)&po, g_o);
    cudaGetSymbolAddress((void**)&ahi, g_ahi);
    cudaGetSymbolAddress((void**)&alo, g_alo);
    cudaGetSymbolAddress((void**)&whi, g_whi);
    cudaGetSymbolAddress((void**)&wlo, g_wlo);

    cudaFuncSetAttribute(mma_proj, cudaFuncAttributeMaxDynamicSharedMemorySize, PROJ_SMEM);
    const int attn_smem = 3 * 64 * 65 * 4;
    cudaFuncSetAttribute(attn_kernel, cudaFuncAttributeMaxDynamicSharedMemorySize, attn_smem);

    const int WN = C_ * C_;  // 262144

    // split inputs / weights into bf16 (hi, lo)
    split_kernel<<<(M_ * C_) / 1024, 256>>>(q_x, ahi, alo, M_ * C_);
    split_kernel<<<WN / 1024, 256>>>(Wq, whi + 0 * WN, wlo + 0 * WN, WN);
    split_kernel<<<WN / 1024, 256>>>(Wk, whi + 1 * WN, wlo + 1 * WN, WN);
    split_kernel<<<WN / 1024, 256>>>(Wv, whi + 2 * WN, wlo + 2 * WN, WN);
    split_kernel<<<WN / 1024, 256>>>(Wg, whi + 3 * WN, wlo + 3 * WN, WN);
    split_kernel<<<WN / 1024, 256>>>(Wo, whi + 4 * WN, wlo + 4 * WN, WN);

    // fused q/k/v/gate projections on tensor cores
    dim3 pgrid(M_ / 128, C_ / 128, 4);   // (32, 4, 4)
    mma_proj<<<pgrid, 256, PROJ_SMEM>>>(ahi, alo, whi, wlo,
                                        bq, bg, gbias, bo, pg,
                                        pq, pk, pv, pg, nullptr, 0);

    // attention (SIMT fp32)
    dim3 agrid(N_ / 64, B_ * H_);
    attn_kernel<<<agrid, 256, attn_smem>>>(pq, pk, pv, bias, po);

    // split attention output, final projection with gating
    split_kernel<<<(M_ * C_) / 1024, 256>>>(po, ahi, alo, M_ * C_);
    dim3 fgrid(M_ / 128, C_ / 128, 1);   // (32, 4)
    mma_proj<<<fgrid, 256, PROJ_SMEM>>>(ahi, alo, whi, wlo,
                                        bq, bg, gbias, bo, pg,
                                        nullptr, nullptr, nullptr, nullptr, out, 1);
}

// round 7
// speedup vs baseline: 3.0130x; 1.8232x over previous
#include <cuda_runtime.h>
#include <cuda_bf16.h>
#include <math.h>
#include <cstdint>

#define B_ 4
#define H_ 8
#define N_ 1024
#define D_ 64
#define C_ 512
#define M_ 4096   // B_*N_

// ---------------- scratch (no allocation allowed) ----------------
__device__ float g_gate[M_ * C_];
__device__ __nv_bfloat16 g_ahi[M_ * C_];
__device__ __nv_bfloat16 g_alo[M_ * C_];
__device__ __nv_bfloat16 g_qhi[M_ * C_];
__device__ __nv_bfloat16 g_qlo[M_ * C_];
__device__ __nv_bfloat16 g_khi[M_ * C_];
__device__ __nv_bfloat16 g_klo[M_ * C_];
__device__ __nv_bfloat16 g_vhi[M_ * C_];
__device__ __nv_bfloat16 g_vlo[M_ * C_];
__device__ __nv_bfloat16 g_ohi[M_ * C_];
__device__ __nv_bfloat16 g_olo[M_ * C_];
__device__ __nv_bfloat16 g_whi[5 * C_ * C_];
__device__ __nv_bfloat16 g_wlo[5 * C_ * C_];

// ---------------- helpers (plain sm_103-safe PTX only) ----------------
__device__ __forceinline__ uint32_t smem_u32(const void* p) {
    uint32_t a;
    asm("{ .reg .u64 t; cvta.to.shared.u64 t, %1; cvt.u32.u64 %0, t; }"
        : "=r"(a) : "l"(p));
    return a;
}
#define SW128(o) ((o) ^ (((o) >> 3) & 0x70))

#define CP_ASYNC16(dst, src) \
    asm volatile("cp.async.cg.shared.global [%0], [%1], 16;" \
                 :: "r"(dst), "l"(src) : "memory")
#define CP_COMMIT() asm volatile("cp.async.commit_group;" ::: "memory")
#define CP_WAIT0()  asm volatile("cp.async.wait_group 0;" ::: "memory")
#define CP_WAIT1()  asm volatile("cp.async.wait_group 1;" ::: "memory")
#define CP_WAIT2()  asm volatile("cp.async.wait_group 2;" ::: "memory")

#define LDSM_X4(r, addr) \
    asm volatile("ldmatrix.sync.aligned.m8n8.x4.shared.b16 {%0,%1,%2,%3}, [%4];" \
                 : "=r"((r)[0]), "=r"((r)[1]), "=r"((r)[2]), "=r"((r)[3]) : "r"(addr))
#define LDSM_X4T(r, addr) \
    asm volatile("ldmatrix.sync.aligned.m8n8.x4.trans.shared.b16 {%0,%1,%2,%3}, [%4];" \
                 : "=r"((r)[0]), "=r"((r)[1]), "=r"((r)[2]), "=r"((r)[3]) : "r"(addr))

__device__ __forceinline__ void mma16816(float* d, const uint32_t* a, const uint32_t* b) {
    asm volatile(
        "mma.sync.aligned.m16n8k16.row.col.f32.bf16.bf16.f32 "
        "{%0,%1,%2,%3}, {%4,%5,%6,%7}, {%8,%9}, {%0,%1,%2,%3};"
        : "+f"(d[0]), "+f"(d[1]), "+f"(d[2]), "+f"(d[3])
        : "r"(a[0]), "r"(a[1]), "r"(a[2]), "r"(a[3]), "r"(b[0]), "r"(b[1]));
}

__device__ __forceinline__ uint32_t pack_bf162(__nv_bfloat16 a, __nv_bfloat16 b) {
    __nv_bfloat162 t = __halves2bfloat162(a, b);
    return *reinterpret_cast<uint32_t*>(&t);
}

// ---------------- fp32 -> (hi, lo) bf16 split ----------------
__global__ __launch_bounds__(256) void split_kernel(
    const float* __restrict__ x, __nv_bfloat16* __restrict__ hi,
    __nv_bfloat16* __restrict__ lo, int n)
{
    int i = (blockIdx.x * 256 + threadIdx.x) * 4;
    if (i >= n) return;
    float4 v = *(const float4*)(x + i);
    float a0 = v.x, a1 = v.y, a2 = v.z, a3 = v.w;
    __nv_bfloat16 h0 = __float2bfloat16(a0), h1 = __float2bfloat16(a1);
    __nv_bfloat16 h2 = __float2bfloat16(a2), h3 = __float2bfloat16(a3);
    __nv_bfloat16 l0 = __float2bfloat16(a0 - __bfloat162float(h0));
    __nv_bfloat16 l1 = __float2bfloat16(a1 - __bfloat162float(h1));
    __nv_bfloat16 l2 = __float2bfloat16(a2 - __bfloat162float(h2));
    __nv_bfloat16 l3 = __float2bfloat16(a3 - __bfloat162float(h3));
    ((__nv_bfloat162*)(hi + i))[0] = __halves2bfloat162(h0, h1);
    ((__nv_bfloat162*)(hi + i))[1] = __halves2bfloat162(h2, h3);
    ((__nv_bfloat162*)(lo + i))[0] = __halves2bfloat162(l0, l1);
    ((__nv_bfloat162*)(lo + i))[1] = __halves2bfloat162(l2, l3);
}

// ---------------- mma.sync projection GEMM ----------------
// z: 0=q (x+bq)*0.125 -> bf16 hi/lo ; 1=k -> hi/lo ; 2=v -> hi/lo ;
// 3=sigmoid(x+bg+gbias) -> fp32 gate ; 4=(x+bo)*gate -> fp32 out
#define TS 16384                   // one tile: 128 rows x 128 bytes
#define PROJ_SMEM (12 * TS)        // 3 stages x 4 tiles

__global__ __launch_bounds__(256, 1) void mma_proj(
    const __nv_bfloat16* __restrict__ Ahi, const __nv_bfloat16* __restrict__ Alo,
    const __nv_bfloat16* __restrict__ Whi_base, const __nv_bfloat16* __restrict__ Wlo_base,
    const float* __restrict__ bq, const float* __restrict__ bg,
    const float* __restrict__ gbias, const float* __restrict__ bo,
    const float* __restrict__ gate,
    __nv_bfloat16* __restrict__ qhi, __nv_bfloat16* __restrict__ qlo,
    __nv_bfloat16* __restrict__ khi, __nv_bfloat16* __restrict__ klo,
    __nv_bfloat16* __restrict__ vhi, __nv_bfloat16* __restrict__ vlo,
    float* __restrict__ gatef, float* __restrict__ outo,
    int final_pass)
{
    extern __shared__ char smem[];
    const uint32_t sb = smem_u32(smem);
    const int tid = threadIdx.x;
    const int lane = tid & 31;
    const int wid = tid >> 5;
    const int wm = wid & 3;
    const int wn = wid >> 2;
    const int m0 = blockIdx.x * 128;
    const int o0 = blockIdx.y * 128;
    const int z = final_pass ? 4 : (int)blockIdx.z;

    const __nv_bfloat16* Whi = Whi_base + (size_t)z * C_ * C_;
    const __nv_bfloat16* Wlo = Wlo_base + (size_t)z * C_ * C_;

    float acc[2][8][4];
#pragma unroll
    for (int i = 0; i < 2; i++)
#pragma unroll
        for (int j = 0; j < 8; j++)
#pragma unroll
            for (int c = 0; c < 4; c++) acc[i][j][c] = 0.f;

    auto issue = [&](int ic) {
        const int buf = ic % 3;
        const uint32_t db = sb + buf * 4 * TS;
        const int k0 = ic * 64;
#pragma unroll
        for (int it = 0; it < 4; it++) {
            int seg = it * 256 + tid;
            int r = seg >> 3;
            int c16 = seg & 7;
            uint32_t sw = SW128((uint32_t)(r * 128 + c16 * 16));
            size_t aoff = (size_t)(m0 + r) * C_ + k0 + c16 * 8;
            size_t woff = (size_t)(o0 + r) * C_ + k0 + c16 * 8;
            CP_ASYNC16(db + 0 * TS + sw, Ahi + aoff);
            CP_ASYNC16(db + 1 * TS + sw, Alo + aoff);
            CP_ASYNC16(db + 2 * TS + sw, Whi + woff);
            CP_ASYNC16(db + 3 * TS + sw, Wlo + woff);
        }
        CP_COMMIT();
    };

    const int a_row = wm * 32 + (lane & 15);
    const int a_kc0 = (lane >> 4) * 8;
    const int b_n   = wn * 64 + (lane & 7) + (lane >> 4) * 8;
    const int b_kc0 = ((lane >> 3) & 1) * 8;

    auto compute = [&](int buf) {
        const uint32_t tb = sb + buf * 4 * TS;
#pragma unroll
        for (int ks = 0; ks < 4; ks++) {
            uint32_t ah[2][4], al[2][4], bf[4][4];
            const int akc = ks * 16 + a_kc0;
            const int bkc = ks * 16 + b_kc0;
#pragma unroll
            for (int mi = 0; mi < 2; mi++) {
                uint32_t off = (uint32_t)((a_row + mi * 16) * 128 + akc * 2);
                LDSM_X4(ah[mi], tb + 0 * TS + SW128(off));
                LDSM_X4(al[mi], tb + 1 * TS + SW128(off));
            }
#pragma unroll
            for (int p = 0; p < 4; p++) {
                uint32_t off = (uint32_t)((b_n + p * 16) * 128 + bkc * 2);
                LDSM_X4(bf[p], tb + 2 * TS + SW128(off));
            }
#pragma unroll
            for (int mi = 0; mi < 2; mi++)
#pragma unroll
                for (int p = 0; p < 4; p++) {
                    mma16816(acc[mi][2 * p + 0], ah[mi], &bf[p][0]);
                    mma16816(acc[mi][2 * p + 1], ah[mi], &bf[p][2]);
                    mma16816(acc[mi][2 * p + 0], al[mi], &bf[p][0]);
                    mma16816(acc[mi][2 * p + 1], al[mi], &bf[p][2]);
                }
#pragma unroll
            for (int p = 0; p < 4; p++) {
                uint32_t off = (uint32_t)((b_n + p * 16) * 128 + bkc * 2);
                LDSM_X4(bf[p], tb + 3 * TS + SW128(off));
            }
#pragma unroll
            for (int mi = 0; mi < 2; mi++)
#pragma unroll
                for (int p = 0; p < 4; p++) {
                    mma16816(acc[mi][2 * p + 0], ah[mi], &bf[p][0]);
                    mma16816(acc[mi][2 * p + 1], ah[mi], &bf[p][2]);
                }
        }
    };

    issue(0); issue(1); issue(2);
    for (int ic = 0; ic < 8; ic++) {
        if (ic < 6) { CP_WAIT2(); }
        else if (ic == 6) { CP_WAIT1(); }
        else { CP_WAIT0(); }
        __syncthreads();
        compute(ic % 3);
        __syncthreads();
        if (ic + 3 < 8) issue(ic + 3);
    }

    // ---- epilogue ----
    auto emit = [&](int m, int c, float v0, float v1) {
        if (z <= 2) {
            if (z == 0) { v0 = (v0 + bq[c]) * 0.125f; v1 = (v1 + bq[c + 1]) * 0.125f; }
            __nv_bfloat16 h0 = __float2bfloat16(v0), h1 = __float2bfloat16(v1);
            __nv_bfloat16 l0 = __float2bfloat16(v0 - __bfloat162float(h0));
            __nv_bfloat16 l1 = __float2bfloat16(v1 - __bfloat162float(h1));
            __nv_bfloat16* oh = (z == 0) ? qhi : (z == 1) ? khi : vhi;
            __nv_bfloat16* ol = (z == 0) ? qlo : (z == 1) ? klo : vlo;
            *(__nv_bfloat162*)(oh + (size_t)m * C_ + c) = __halves2bfloat162(h0, h1);
            *(__nv_bfloat162*)(ol + (size_t)m * C_ + c) = __halves2bfloat162(l0, l1);
        } else if (z == 3) {
            v0 = 1.f / (1.f + __expf(-(v0 + bg[c] + gbias[c])));
            v1 = 1.f / (1.f + __expf(-(v1 + bg[c + 1] + gbias[c + 1])));
            *(float2*)(gatef + (size_t)m * C_ + c) = make_float2(v0, v1);
        } else {
            v0 = (v0 + bo[c]) * gate[(size_t)m * C_ + c];
            v1 = (v1 + bo[c + 1]) * gate[(size_t)m * C_ + c + 1];
            *(float2*)(outo + (size_t)m * C_ + c) = make_float2(v0, v1);
        }
    };

#pragma unroll
    for (int mi = 0; mi < 2; mi++)
#pragma unroll
        for (int nj = 0; nj < 8; nj++) {
            int row = m0 + wm * 32 + mi * 16 + (lane >> 2);
            int col = o0 + wn * 64 + nj * 8 + (lane & 3) * 2;
            emit(row,     col, acc[mi][nj][0], acc[mi][nj][1]);
            emit(row + 8, col, acc[mi][nj][2], acc[mi][nj][3]);
        }
}

// ---------------- tensor-core flash attention with bias ----------------
// grid (N_/128, B_*H_); 256 threads; warp w owns query rows [w*16, w*16+16).
// smem: Qhi 16K, Qlo 16K, then 2 KV buffers of {Khi,Klo,Vhi,Vlo} 8K each.
#define AT_KV0 32768
#define AT_BUFS 32768
#define ATT_SMEM (AT_KV0 + 2 * AT_BUFS)   // 98304

__global__ __launch_bounds__(256, 1) void attn_mma(
    const __nv_bfloat16* __restrict__ qhi, const __nv_bfloat16* __restrict__ qlo,
    const __nv_bfloat16* __restrict__ khi, const __nv_bfloat16* __restrict__ klo,
    const __nv_bfloat16* __restrict__ vhi, const __nv_bfloat16* __restrict__ vlo,
    const float* __restrict__ bias,
    __nv_bfloat16* __restrict__ ohi, __nv_bfloat16* __restrict__ olo)
{
    extern __shared__ char smem[];
    const uint32_t sb = smem_u32(smem);
    const int tid = threadIdx.x;
    const int lane = tid & 31;
    const int wid = tid >> 5;           // 0..7 -> m offset wid*16
    const int qt = blockIdx.x;
    const int bh = blockIdx.y;
    const int b = bh >> 3, h = bh & 7;
    const int q0 = qt * 128;

    const size_t qbase  = (size_t)(b * N_ + q0) * C_ + h * 64;
    const size_t kvbase = (size_t)(b * N_) * C_ + h * 64;
    const float* biasb = bias + (size_t)bh * N_ * N_;

    // ---- prologue: load Q tiles + KV chunk 0 (group 0), KV chunk 1 (group 1)
    {
#pragma unroll
        for (int it = 0; it < 4; it++) {
            int seg = it * 256 + tid;       // 0..1023
            int r = seg >> 3;               // 0..127
            int c16 = seg & 7;
            uint32_t sw = SW128((uint32_t)(r * 128 + c16 * 16));
            size_t off = qbase + (size_t)r * C_ + c16 * 8;
            CP_ASYNC16(sb + sw, qhi + off);
            CP_ASYNC16(sb + 16384 + sw, qlo + off);
        }
    }
    auto issue_kv = [&](int kc) {
        const uint32_t db = sb + AT_KV0 + (kc & 1) * AT_BUFS;
#pragma unroll
        for (int it = 0; it < 2; it++) {
            int seg = it * 256 + tid;       // 0..511
            int r = seg >> 3;               // 0..63
            int c16 = seg & 7;
            uint32_t sw = SW128((uint32_t)(r * 128 + c16 * 16));
            size_t off = kvbase + (size_t)(kc * 64 + r) * C_ + c16 * 8;
            CP_ASYNC16(db + 0 * 8192 + sw, khi + off);
            CP_ASYNC16(db + 1 * 8192 + sw, klo + off);
            CP_ASYNC16(db + 2 * 8192 + sw, vhi + off);
            CP_ASYNC16(db + 3 * 8192 + sw, vlo + off);
        }
        CP_COMMIT();
    };
    issue_kv(0);   // group 0 (with Q)
    issue_kv(1);   // group 1

    // ---- Q fragments (resident): 4 k-steps x 4 regs, hi and lo
    uint32_t qh[4][4], ql[4][4];

    float o[8][4];
    float m0r = -1e30f, m1r = -1e30f, l0r = 0.f, l1r = 0.f;
#pragma unroll
    for (int j = 0; j < 8; j++)
#pragma unroll
        for (int c = 0; c < 4; c++) o[j][c] = 0.f;

    const int a_row = wid * 16 + (lane & 15);
    const int a_kc0 = (lane >> 4) * 8;
    const int bn_row = (lane & 7) + (lane >> 4) * 8;    // K non-trans n index
    const int bn_kc0 = ((lane >> 3) & 1) * 8;
    const int vt_row = (lane & 15);                      // V trans: key index
    const int vt_c0  = (lane >> 4) * 8;                  // V trans: d offset

    bool qloaded = false;

    for (int kc = 0; kc < 16; kc++) {
        if (kc < 15) { CP_WAIT1(); } else { CP_WAIT0(); }
        __syncthreads();

        if (!qloaded) {
            qloaded = true;
#pragma unroll
            for (int ks = 0; ks < 4; ks++) {
                uint32_t off = SW128((uint32_t)(a_row * 128 + (ks * 16 + a_kc0) * 2));
                LDSM_X4(qh[ks], sb + off);
                LDSM_X4(ql[ks], sb + 16384 + off);
            }
        }

        // bias prefetch into registers (rows r, r+8; cols per n-group)
        float2 bv[8][2];
        {
            const int r0g = q0 + wid * 16 + (lane >> 2);
            const size_t rowoff0 = (size_t)r0g * N_ + kc * 64 + 2 * (lane & 3);
            const size_t rowoff1 = rowoff0 + (size_t)8 * N_;
#pragma unroll
            for (int j = 0; j < 8; j++) {
                bv[j][0] = *(const float2*)(biasb + rowoff0 + 8 * j);
                bv[j][1] = *(const float2*)(biasb + rowoff1 + 8 * j);
            }
        }

        const uint32_t tb = sb + AT_KV0 + (kc & 1) * AT_BUFS;

        // ---- S = Q K^T (3-term bf16 split)
        float s[8][4];
#pragma unroll
        for (int j = 0; j < 8; j++)
#pragma unroll
            for (int c = 0; c < 4; c++) s[j][c] = 0.f;

#pragma unroll
        for (int ks = 0; ks < 4; ks++) {
#pragma unroll
            for (int p = 0; p < 4; p++) {
                uint32_t kh[4], kl[4];
                uint32_t off = SW128((uint32_t)((p * 16 + bn_row) * 128 +
                                                (ks * 16 + bn_kc0) * 2));
                LDSM_X4(kh, tb + 0 * 8192 + off);
                mma16816(s[2 * p + 0], qh[ks], &kh[0]);
                mma16816(s[2 * p + 1], qh[ks], &kh[2]);
                mma16816(s[2 * p + 0], ql[ks], &kh[0]);
                mma16816(s[2 * p + 1], ql[ks], &kh[2]);
                LDSM_X4(kl, tb + 1 * 8192 + off);
                mma16816(s[2 * p + 0], qh[ks], &kl[0]);
                mma16816(s[2 * p + 1], qh[ks], &kl[2]);
            }
        }

        // ---- S += bias
#pragma unroll
        for (int j = 0; j < 8; j++) {
            s[j][0] += bv[j][0].x; s[j][1] += bv[j][0].y;
            s[j][2] += bv[j][1].x; s[j][3] += bv[j][1].y;
        }

        // ---- online softmax (rows r=lane>>2 and r+8; quad shuffles)
        float mt0 = -1e30f, mt1 = -1e30f;
#pragma unroll
        for (int j = 0; j < 8; j++) {
            mt0 = fmaxf(mt0, fmaxf(s[j][0], s[j][1]));
            mt1 = fmaxf(mt1, fmaxf(s[j][2], s[j][3]));
        }
        mt0 = fmaxf(mt0, __shfl_xor_sync(0xffffffffu, mt0, 1));
        mt0 = fmaxf(mt0, __shfl_xor_sync(0xffffffffu, mt0, 2));
        mt1 = fmaxf(mt1, __shfl_xor_sync(0xffffffffu, mt1, 1));
        mt1 = fmaxf(mt1, __shfl_xor_sync(0xffffffffu, mt1, 2));

        float mn0 = fmaxf(m0r, mt0), mn1 = fmaxf(m1r, mt1);
        float al0 = __expf(m0r - mn0), al1 = __expf(m1r - mn1);
        m0r = mn0; m1r = mn1;

        float sum0 = 0.f, sum1 = 0.f;
        uint32_t phi[4][4], plo[4][4];
#pragma unroll
        for (int j = 0; j < 8; j++) {
            s[j][0] = __expf(s[j][0] - mn0); s[j][1] = __expf(s[j][1] - mn0);
            s[j][2] = __expf(s[j][2] - mn1); s[j][3] = __expf(s[j][3] - mn1);
            sum0 += s[j][0] + s[j][1];
            sum1 += s[j][2] + s[j][3];
        }
#pragma unroll
        for (int ks = 0; ks < 4; ks++) {
#pragma unroll
            for (int half = 0; half < 2; half++) {
                const int j = 2 * ks + half;
                __nv_bfloat16 h0 = __float2bfloat16(s[j][0]);
                __nv_bfloat16 h1 = __float2bfloat16(s[j][1]);
                __nv_bfloat16 h2 = __float2bfloat16(s[j][2]);
                __nv_bfloat16 h3 = __float2bfloat16(s[j][3]);
                phi[ks][2 * half + 0] = pack_bf162(h0, h1);
                phi[ks][2 * half + 1] = pack_bf162(h2, h3);
                plo[ks][2 * half + 0] = pack_bf162(
                    __float2bfloat16(s[j][0] - __bfloat162float(h0)),
                    __float2bfloat16(s[j][1] - __bfloat162float(h1)));
                plo[ks][2 * half + 1] = pack_bf162(
                    __float2bfloat16(s[j][2] - __bfloat162float(h2)),
                    __float2bfloat16(s[j][3] - __bfloat162float(h3)));
            }
        }
        sum0 += __shfl_xor_sync(0xffffffffu, sum0, 1);
        sum0 += __shfl_xor_sync(0xffffffffu, sum0, 2);
        sum1 += __shfl_xor_sync(0xffffffffu, sum1, 1);
        sum1 += __shfl_xor_sync(0xffffffffu, sum1, 2);
        l0r = l0r * al0 + sum0;
        l1r = l1r * al1 + sum1;

#pragma unroll
        for (int j = 0; j < 8; j++) {
            o[j][0] *= al0; o[j][1] *= al0;
            o[j][2] *= al1; o[j][3] *= al1;
        }

        // ---- O += P V (3-term; V via ldmatrix.trans on [key][d] tiles)
#pragma unroll
        for (int ks = 0; ks < 4; ks++) {
#pragma unroll
            for (int dp = 0; dp < 4; dp++) {
                uint32_t vh[4], vl[4];
                uint32_t off = SW128((uint32_t)((ks * 16 + vt_row) * 128 +
                                                (dp * 16 + vt_c0) * 2));
                LDSM_X4T(vh, tb + 2 * 8192 + off);
                mma16816(o[2 * dp + 0], phi[ks], &vh[0]);
                mma16816(o[2 * dp + 1], phi[ks], &vh[2]);
                mma16816(o[2 * dp + 0], plo[ks], &vh[0]);
                mma16816(o[2 * dp + 1], plo[ks], &vh[2]);
                LDSM_X4T(vl, tb + 3 * 8192 + off);
                mma16816(o[2 * dp + 0], phi[ks], &vl[0]);
                mma16816(o[2 * dp + 1], phi[ks], &vl[2]);
            }
        }

        __syncthreads();
        if (kc + 2 < 16) issue_kv(kc + 2);
    }

    // ---- epilogue: o/l -> bf16 hi/lo
    const float inv0 = 1.f / l0r, inv1 = 1.f / l1r;
    const int row0 = q0 + wid * 16 + (lane >> 2);
#pragma unroll
    for (int j = 0; j < 8; j++) {
        const int col = h * 64 + 8 * j + 2 * (lane & 3);
        float e0 = o[j][0] * inv0, e1 = o[j][1] * inv0;
        float e2 = o[j][2] * inv1, e3 = o[j][3] * inv1;
        __nv_bfloat16 h0 = __float2bfloat16(e0), h1 = __float2bfloat16(e1);
        __nv_bfloat16 h2 = __float2bfloat16(e2), h3 = __float2bfloat16(e3);
        size_t off0 = (size_t)(b * N_ + row0) * C_ + col;
        size_t off1 = (size_t)(b * N_ + row0 + 8) * C_ + col;
        *(__nv_bfloat162*)(ohi + off0) = __halves2bfloat162(h0, h1);
        *(__nv_bfloat162*)(olo + off0) = __halves2bfloat162(
            __float2bfloat16(e0 - __bfloat162float(h0)),
            __float2bfloat16(e1 - __bfloat162float(h1)));
        *(__nv_bfloat162*)(ohi + off1) = __halves2bfloat162(h2, h3);
        *(__nv_bfloat162*)(olo + off1) = __halves2bfloat162(
            __float2bfloat16(e2 - __bfloat162float(h2)),
            __float2bfloat16(e3 - __bfloat162float(h3)));
    }
}

// ---------------------------------------------------------------------------
extern "C" void kernel_launch(void* const* d_in, const int* in_sizes, int n_in,
                              void* d_out, int out_size)
{
    const float* q_x   = (const float*)d_in[0];
    const float* bias  = (const float*)d_in[1];
    const float* Wq    = (const float*)d_in[2];
    const float* bq    = (const float*)d_in[3];
    const float* Wk    = (const float*)d_in[4];
    const float* Wv    = (const float*)d_in[5];
    const float* Wo    = (const float*)d_in[6];
    const float* bo    = (const float*)d_in[7];
    const float* Wg    = (const float*)d_in[8];
    const float* bg    = (const float*)d_in[9];
    const float* gbias = (const float*)d_in[10];
    float* out = (float*)d_out;

    float* pg;
    __nv_bfloat16 *ahi, *alo, *whi, *wlo;
    __nv_bfloat16 *qh, *ql, *kh, *kl, *vh, *vl, *oh, *ol;
    cudaGetSymbolAddress((void**)&pg, g_gate);
    cudaGetSymbolAddress((void**)&ahi, g_ahi);
    cudaGetSymbolAddress((void**)&alo, g_alo);
    cudaGetSymbolAddress((void**)&whi, g_whi);
    cudaGetSymbolAddress((void**)&wlo, g_wlo);
    cudaGetSymbolAddress((void**)&qh, g_qhi);
    cudaGetSymbolAddress((void**)&ql, g_qlo);
    cudaGetSymbolAddress((void**)&kh, g_khi);
    cudaGetSymbolAddress((void**)&kl, g_klo);
    cudaGetSymbolAddress((void**)&vh, g_vhi);
    cudaGetSymbolAddress((void**)&vl, g_vlo);
    cudaGetSymbolAddress((void**)&oh, g_ohi);
    cudaGetSymbolAddress((void**)&ol, g_olo);

    cudaFuncSetAttribute(mma_proj, cudaFuncAttributeMaxDynamicSharedMemorySize, PROJ_SMEM);
    cudaFuncSetAttribute(attn_mma, cudaFuncAttributeMaxDynamicSharedMemorySize, ATT_SMEM);

    const int WN = C_ * C_;

    split_kernel<<<(M_ * C_) / 1024, 256>>>(q_x, ahi, alo, M_ * C_);
    split_kernel<<<WN / 1024, 256>>>(Wq, whi + 0 * WN, wlo + 0 * WN, WN);
    split_kernel<<<WN / 1024, 256>>>(Wk, whi + 1 * WN, wlo + 1 * WN, WN);
    split_kernel<<<WN / 1024, 256>>>(Wv, whi + 2 * WN, wlo + 2 * WN, WN);
    split_kernel<<<WN / 1024, 256>>>(Wg, whi + 3 * WN, wlo + 3 * WN, WN);
    split_kernel<<<WN / 1024, 256>>>(Wo, whi + 4 * WN, wlo + 4 * WN, WN);

    // fused q/k/v/gate projections (bf16 hi/lo outputs for q,k,v; fp32 gate)
    dim3 pgrid(M_ / 128, C_ / 128, 4);
    mma_proj<<<pgrid, 256, PROJ_SMEM>>>(ahi, alo, whi, wlo,
                                        bq, bg, gbias, bo, pg,
                                        qh, ql, kh, kl, vh, vl, pg, nullptr, 0);

    // tensor-core attention -> bf16 hi/lo output
    dim3 agrid(N_ / 128, B_ * H_);
    attn_mma<<<agrid, 256, ATT_SMEM>>>(qh, ql, kh, kl, vh, vl, bias, oh, ol);

    // final gated projection (fp32 out)
    dim3 fgrid(M_ / 128, C_ / 128, 1);
    mma_proj<<<fgrid, 256, PROJ_SMEM>>>(oh, ol, whi, wlo,
                                        bq, bg, gbias, bo, pg,
                                        nullptr, nullptr, nullptr, nullptr, nullptr, nullptr,
                                        nullptr, out, 1);
}

// round 13
// speedup vs baseline: 3.1448x; 1.0438x over previous
#include <cuda_runtime.h>
#include <cuda_bf16.h>
#include <math.h>
#include <cstdint>

#define B_ 4
#define H_ 8
#define N_ 1024
#define D_ 64
#define C_ 512
#define M_ 4096   // B_*N_

// ---------------- scratch (no allocation allowed) ----------------
__device__ float g_gate[M_ * C_];
__device__ __nv_bfloat16 g_ahi[M_ * C_];
__device__ __nv_bfloat16 g_alo[M_ * C_];
__device__ __nv_bfloat16 g_qhi[M_ * C_];
__device__ __nv_bfloat16 g_qlo[M_ * C_];
__device__ __nv_bfloat16 g_khi[M_ * C_];
__device__ __nv_bfloat16 g_klo[M_ * C_];
__device__ __nv_bfloat16 g_vhi[M_ * C_];
__device__ __nv_bfloat16 g_vlo[M_ * C_];
__device__ __nv_bfloat16 g_ohi[M_ * C_];
__device__ __nv_bfloat16 g_olo[M_ * C_];
__device__ __nv_bfloat16 g_whi[5 * C_ * C_];
__device__ __nv_bfloat16 g_wlo[5 * C_ * C_];

// ---------------- helpers (plain sm_103-safe PTX only) ----------------
__device__ __forceinline__ uint32_t smem_u32(const void* p) {
    uint32_t a;
    asm("{ .reg .u64 t; cvta.to.shared.u64 t, %1; cvt.u32.u64 %0, t; }"
        : "=r"(a) : "l"(p));
    return a;
}
#define SW128(o) ((o) ^ (((o) >> 3) & 0x70))

#define CP_ASYNC16(dst, src) \
    asm volatile("cp.async.cg.shared.global [%0], [%1], 16;" \
                 :: "r"(dst), "l"(src) : "memory")
#define CP_COMMIT() asm volatile("cp.async.commit_group;" ::: "memory")
#define CP_WAIT0()  asm volatile("cp.async.wait_group 0;" ::: "memory")
#define CP_WAIT1()  asm volatile("cp.async.wait_group 1;" ::: "memory")
#define CP_WAIT2()  asm volatile("cp.async.wait_group 2;" ::: "memory")

#define LDSM_X4(r, addr) \
    asm volatile("ldmatrix.sync.aligned.m8n8.x4.shared.b16 {%0,%1,%2,%3}, [%4];" \
                 : "=r"((r)[0]), "=r"((r)[1]), "=r"((r)[2]), "=r"((r)[3]) : "r"(addr))
#define LDSM_X4T(r, addr) \
    asm volatile("ldmatrix.sync.aligned.m8n8.x4.trans.shared.b16 {%0,%1,%2,%3}, [%4];" \
                 : "=r"((r)[0]), "=r"((r)[1]), "=r"((r)[2]), "=r"((r)[3]) : "r"(addr))

__device__ __forceinline__ void mma16816(float* d, const uint32_t* a, const uint32_t* b) {
    asm volatile(
        "mma.sync.aligned.m16n8k16.row.col.f32.bf16.bf16.f32 "
        "{%0,%1,%2,%3}, {%4,%5,%6,%7}, {%8,%9}, {%0,%1,%2,%3};"
        : "+f"(d[0]), "+f"(d[1]), "+f"(d[2]), "+f"(d[3])
        : "r"(a[0]), "r"(a[1]), "r"(a[2]), "r"(a[3]), "r"(b[0]), "r"(b[1]));
}

__device__ __forceinline__ uint32_t pack_bf162(__nv_bfloat16 a, __nv_bfloat16 b) {
    __nv_bfloat162 t = __halves2bfloat162(a, b);
    return *reinterpret_cast<uint32_t*>(&t);
}

// ---------------- fp32 -> (hi, lo) bf16 split ----------------
__global__ __launch_bounds__(256) void split_kernel(
    const float* __restrict__ x, __nv_bfloat16* __restrict__ hi,
    __nv_bfloat16* __restrict__ lo, int n)
{
    int i = (blockIdx.x * 256 + threadIdx.x) * 4;
    if (i >= n) return;
    float4 v = *(const float4*)(x + i);
    float a0 = v.x, a1 = v.y, a2 = v.z, a3 = v.w;
    __nv_bfloat16 h0 = __float2bfloat16(a0), h1 = __float2bfloat16(a1);
    __nv_bfloat16 h2 = __float2bfloat16(a2), h3 = __float2bfloat16(a3);
    __nv_bfloat16 l0 = __float2bfloat16(a0 - __bfloat162float(h0));
    __nv_bfloat16 l1 = __float2bfloat16(a1 - __bfloat162float(h1));
    __nv_bfloat16 l2 = __float2bfloat16(a2 - __bfloat162float(h2));
    __nv_bfloat16 l3 = __float2bfloat16(a3 - __bfloat162float(h3));
    ((__nv_bfloat162*)(hi + i))[0] = __halves2bfloat162(h0, h1);
    ((__nv_bfloat162*)(hi + i))[1] = __halves2bfloat162(h2, h3);
    ((__nv_bfloat162*)(lo + i))[0] = __halves2bfloat162(l0, l1);
    ((__nv_bfloat162*)(lo + i))[1] = __halves2bfloat162(l2, l3);
}

// one launch for all 5 weight matrices (they land contiguously in g_whi/g_wlo)
struct WPtrs { const float* p[5]; };
__global__ __launch_bounds__(256) void split5_kernel(
    WPtrs w, __nv_bfloat16* __restrict__ hi, __nv_bfloat16* __restrict__ lo)
{
    const int WN = C_ * C_;
    int i = (blockIdx.x * 256 + threadIdx.x) * 4;
    if (i >= 5 * WN) return;
    int region = i / WN;
    int off = i - region * WN;
    float4 v = *(const float4*)(w.p[region] + off);
    float a0 = v.x, a1 = v.y, a2 = v.z, a3 = v.w;
    __nv_bfloat16 h0 = __float2bfloat16(a0), h1 = __float2bfloat16(a1);
    __nv_bfloat16 h2 = __float2bfloat16(a2), h3 = __float2bfloat16(a3);
    __nv_bfloat16 l0 = __float2bfloat16(a0 - __bfloat162float(h0));
    __nv_bfloat16 l1 = __float2bfloat16(a1 - __bfloat162float(h1));
    __nv_bfloat16 l2 = __float2bfloat16(a2 - __bfloat162float(h2));
    __nv_bfloat16 l3 = __float2bfloat16(a3 - __bfloat162float(h3));
    ((__nv_bfloat162*)(hi + i))[0] = __halves2bfloat162(h0, h1);
    ((__nv_bfloat162*)(hi + i))[1] = __halves2bfloat162(h2, h3);
    ((__nv_bfloat162*)(lo + i))[0] = __halves2bfloat162(l0, l1);
    ((__nv_bfloat162*)(lo + i))[1] = __halves2bfloat162(l2, l3);
}

// ---------------- mma.sync projection GEMM ----------------
// z: 0=q (x+bq)*0.125 -> bf16 hi/lo ; 1=k -> hi/lo ; 2=v -> hi/lo ;
// 3=sigmoid(x+bg+gbias) -> fp32 gate ; 4=(x+bo)*gate -> fp32 out
#define TS 16384                   // one tile: 128 rows x 128 bytes
#define PROJ_SMEM (12 * TS)        // 3 stages x 4 tiles

__global__ __launch_bounds__(256, 1) void mma_proj(
    const __nv_bfloat16* __restrict__ Ahi, const __nv_bfloat16* __restrict__ Alo,
    const __nv_bfloat16* __restrict__ Whi_base, const __nv_bfloat16* __restrict__ Wlo_base,
    const float* __restrict__ bq, const float* __restrict__ bg,
    const float* __restrict__ gbias, const float* __restrict__ bo,
    const float* __restrict__ gate,
    __nv_bfloat16* __restrict__ qhi, __nv_bfloat16* __restrict__ qlo,
    __nv_bfloat16* __restrict__ khi, __nv_bfloat16* __restrict__ klo,
    __nv_bfloat16* __restrict__ vhi, __nv_bfloat16* __restrict__ vlo,
    float* __restrict__ gatef, float* __restrict__ outo,
    int final_pass)
{
    extern __shared__ char smem[];
    const uint32_t sb = smem_u32(smem);
    const int tid = threadIdx.x;
    const int lane = tid & 31;
    const int wid = tid >> 5;
    const int wm = wid & 3;
    const int wn = wid >> 2;
    const int m0 = blockIdx.x * 128;
    const int o0 = blockIdx.y * 128;
    const int z = final_pass ? 4 : (int)blockIdx.z;

    const __nv_bfloat16* Whi = Whi_base + (size_t)z * C_ * C_;
    const __nv_bfloat16* Wlo = Wlo_base + (size_t)z * C_ * C_;

    float acc[2][8][4];
#pragma unroll
    for (int i = 0; i < 2; i++)
#pragma unroll
        for (int j = 0; j < 8; j++)
#pragma unroll
            for (int c = 0; c < 4; c++) acc[i][j][c] = 0.f;

    auto issue = [&](int ic) {
        const int buf = ic % 3;
        const uint32_t db = sb + buf * 4 * TS;
        const int k0 = ic * 64;
#pragma unroll
        for (int it = 0; it < 4; it++) {
            int seg = it * 256 + tid;
            int r = seg >> 3;
            int c16 = seg & 7;
            uint32_t sw = SW128((uint32_t)(r * 128 + c16 * 16));
            size_t aoff = (size_t)(m0 + r) * C_ + k0 + c16 * 8;
            size_t woff = (size_t)(o0 + r) * C_ + k0 + c16 * 8;
            CP_ASYNC16(db + 0 * TS + sw, Ahi + aoff);
            CP_ASYNC16(db + 1 * TS + sw, Alo + aoff);
            CP_ASYNC16(db + 2 * TS + sw, Whi + woff);
            CP_ASYNC16(db + 3 * TS + sw, Wlo + woff);
        }
        CP_COMMIT();
    };

    const int a_row = wm * 32 + (lane & 15);
    const int a_kc0 = (lane >> 4) * 8;
    const int b_n   = wn * 64 + (lane & 7) + (lane >> 4) * 8;
    const int b_kc0 = ((lane >> 3) & 1) * 8;

    auto compute = [&](int buf) {
        const uint32_t tb = sb + buf * 4 * TS;
#pragma unroll
        for (int ks = 0; ks < 4; ks++) {
            uint32_t ah[2][4], al[2][4], bf[4][4];
            const int akc = ks * 16 + a_kc0;
            const int bkc = ks * 16 + b_kc0;
#pragma unroll
            for (int mi = 0; mi < 2; mi++) {
                uint32_t off = (uint32_t)((a_row + mi * 16) * 128 + akc * 2);
                LDSM_X4(ah[mi], tb + 0 * TS + SW128(off));
                LDSM_X4(al[mi], tb + 1 * TS + SW128(off));
            }
#pragma unroll
            for (int p = 0; p < 4; p++) {
                uint32_t off = (uint32_t)((b_n + p * 16) * 128 + bkc * 2);
                LDSM_X4(bf[p], tb + 2 * TS + SW128(off));
            }
#pragma unroll
            for (int mi = 0; mi < 2; mi++)
#pragma unroll
                for (int p = 0; p < 4; p++) {
                    mma16816(acc[mi][2 * p + 0], ah[mi], &bf[p][0]);
                    mma16816(acc[mi][2 * p + 1], ah[mi], &bf[p][2]);
                    mma16816(acc[mi][2 * p + 0], al[mi], &bf[p][0]);
                    mma16816(acc[mi][2 * p + 1], al[mi], &bf[p][2]);
                }
#pragma unroll
            for (int p = 0; p < 4; p++) {
                uint32_t off = (uint32_t)((b_n + p * 16) * 128 + bkc * 2);
                LDSM_X4(bf[p], tb + 3 * TS + SW128(off));
            }
#pragma unroll
            for (int mi = 0; mi < 2; mi++)
#pragma unroll
                for (int p = 0; p < 4; p++) {
                    mma16816(acc[mi][2 * p + 0], ah[mi], &bf[p][0]);
                    mma16816(acc[mi][2 * p + 1], ah[mi], &bf[p][2]);
                }
        }
    };

    issue(0); issue(1); issue(2);
    for (int ic = 0; ic < 8; ic++) {
        if (ic < 6) { CP_WAIT2(); }
        else if (ic == 6) { CP_WAIT1(); }
        else { CP_WAIT0(); }
        __syncthreads();
        compute(ic % 3);
        __syncthreads();
        if (ic + 3 < 8) issue(ic + 3);
    }

    // ---- epilogue ----
    auto emit = [&](int m, int c, float v0, float v1) {
        if (z <= 2) {
            if (z == 0) { v0 = (v0 + bq[c]) * 0.125f; v1 = (v1 + bq[c + 1]) * 0.125f; }
            __nv_bfloat16 h0 = __float2bfloat16(v0), h1 = __float2bfloat16(v1);
            __nv_bfloat16 l0 = __float2bfloat16(v0 - __bfloat162float(h0));
            __nv_bfloat16 l1 = __float2bfloat16(v1 - __bfloat162float(h1));
            __nv_bfloat16* oh = (z == 0) ? qhi : (z == 1) ? khi : vhi;
            __nv_bfloat16* ol = (z == 0) ? qlo : (z == 1) ? klo : vlo;
            *(__nv_bfloat162*)(oh + (size_t)m * C_ + c) = __halves2bfloat162(h0, h1);
            *(__nv_bfloat162*)(ol + (size_t)m * C_ + c) = __halves2bfloat162(l0, l1);
        } else if (z == 3) {
            v0 = 1.f / (1.f + __expf(-(v0 + bg[c] + gbias[c])));
            v1 = 1.f / (1.f + __expf(-(v1 + bg[c + 1] + gbias[c + 1])));
            *(float2*)(gatef + (size_t)m * C_ + c) = make_float2(v0, v1);
        } else {
            v0 = (v0 + bo[c]) * gate[(size_t)m * C_ + c];
            v1 = (v1 + bo[c + 1]) * gate[(size_t)m * C_ + c + 1];
            *(float2*)(outo + (size_t)m * C_ + c) = make_float2(v0, v1);
        }
    };

#pragma unroll
    for (int mi = 0; mi < 2; mi++)
#pragma unroll
        for (int nj = 0; nj < 8; nj++) {
            int row = m0 + wm * 32 + mi * 16 + (lane >> 2);
            int col = o0 + wn * 64 + nj * 8 + (lane & 3) * 2;
            emit(row,     col, acc[mi][nj][0], acc[mi][nj][1]);
            emit(row + 8, col, acc[mi][nj][2], acc[mi][nj][3]);
        }
}

// ---------------- tensor-core flash attention with bias ----------------
// grid (N_/128, B_*H_); 256 threads; warp w owns query rows [w*16, w*16+16).
// smem: Qhi 16K, Qlo 16K, then 2 KV buffers of {Khi,Klo,Vhi,Vlo} 8K each.
// Bias is loaded directly into the S accumulators (mma d = a*b + d).
#define AT_KV0 32768
#define AT_BUFS 32768
#define ATT_SMEM (AT_KV0 + 2 * AT_BUFS)   // 98304

__global__ __launch_bounds__(256, 2) void attn_mma(
    const __nv_bfloat16* __restrict__ qhi, const __nv_bfloat16* __restrict__ qlo,
    const __nv_bfloat16* __restrict__ khi, const __nv_bfloat16* __restrict__ klo,
    const __nv_bfloat16* __restrict__ vhi, const __nv_bfloat16* __restrict__ vlo,
    const float* __restrict__ bias,
    __nv_bfloat16* __restrict__ ohi, __nv_bfloat16* __restrict__ olo)
{
    extern __shared__ char smem[];
    const uint32_t sb = smem_u32(smem);
    const int tid = threadIdx.x;
    const int lane = tid & 31;
    const int wid = tid >> 5;           // 0..7 -> m offset wid*16
    const int qt = blockIdx.x;
    const int bh = blockIdx.y;
    const int b = bh >> 3, h = bh & 7;
    const int q0 = qt * 128;

    const size_t qbase  = (size_t)(b * N_ + q0) * C_ + h * 64;
    const size_t kvbase = (size_t)(b * N_) * C_ + h * 64;
    const float* biasb = bias + (size_t)bh * N_ * N_;

    // ---- prologue: load Q tiles + KV chunk 0 (group 0), KV chunk 1 (group 1)
    {
#pragma unroll
        for (int it = 0; it < 4; it++) {
            int seg = it * 256 + tid;       // 0..1023
            int r = seg >> 3;               // 0..127
            int c16 = seg & 7;
            uint32_t sw = SW128((uint32_t)(r * 128 + c16 * 16));
            size_t off = qbase + (size_t)r * C_ + c16 * 8;
            CP_ASYNC16(sb + sw, qhi + off);
            CP_ASYNC16(sb + 16384 + sw, qlo + off);
        }
    }
    auto issue_kv = [&](int kc) {
        const uint32_t db = sb + AT_KV0 + (kc & 1) * AT_BUFS;
#pragma unroll
        for (int it = 0; it < 2; it++) {
            int seg = it * 256 + tid;       // 0..511
            int r = seg >> 3;               // 0..63
            int c16 = seg & 7;
            uint32_t sw = SW128((uint32_t)(r * 128 + c16 * 16));
            size_t off = kvbase + (size_t)(kc * 64 + r) * C_ + c16 * 8;
            CP_ASYNC16(db + 0 * 8192 + sw, khi + off);
            CP_ASYNC16(db + 1 * 8192 + sw, klo + off);
            CP_ASYNC16(db + 2 * 8192 + sw, vhi + off);
            CP_ASYNC16(db + 3 * 8192 + sw, vlo + off);
        }
        CP_COMMIT();
    };
    issue_kv(0);   // group 0 (with Q)
    issue_kv(1);   // group 1

    uint32_t qh[4][4], ql[4][4];

    float o[8][4];
    float m0r = -1e30f, m1r = -1e30f, l0r = 0.f, l1r = 0.f;
#pragma unroll
    for (int j = 0; j < 8; j++)
#pragma unroll
        for (int c = 0; c < 4; c++) o[j][c] = 0.f;

    const int a_row = wid * 16 + (lane & 15);
    const int a_kc0 = (lane >> 4) * 8;
    const int bn_row = (lane & 7) + (lane >> 4) * 8;
    const int bn_kc0 = ((lane >> 3) & 1) * 8;
    const int vt_row = (lane & 15);
    const int vt_c0  = (lane >> 4) * 8;

    // bias row pointers for this thread (rows r, r+8 of the C-fragment)
    const int r0g = q0 + wid * 16 + (lane >> 2);
    const float* bp0 = biasb + (size_t)r0g * N_ + 2 * (lane & 3);
    const float* bp1 = bp0 + (size_t)8 * N_;

    bool qloaded = false;

    for (int kc = 0; kc < 16; kc++) {
        // ---- S init = bias (mma accumulates q.k on top)
        float s[8][4];
        {
            const float* b0 = bp0 + kc * 64;
            const float* b1 = bp1 + kc * 64;
#pragma unroll
            for (int j = 0; j < 8; j++) {
                float2 t0 = *(const float2*)(b0 + 8 * j);
                float2 t1 = *(const float2*)(b1 + 8 * j);
                s[j][0] = t0.x; s[j][1] = t0.y; s[j][2] = t1.x; s[j][3] = t1.y;
            }
        }

        if (kc < 15) { CP_WAIT1(); } else { CP_WAIT0(); }
        __syncthreads();

        if (!qloaded) {
            qloaded = true;
#pragma unroll
            for (int ks = 0; ks < 4; ks++) {
                uint32_t off = SW128((uint32_t)(a_row * 128 + (ks * 16 + a_kc0) * 2));
                LDSM_X4(qh[ks], sb + off);
                LDSM_X4(ql[ks], sb + 16384 + off);
            }
        }

        const uint32_t tb = sb + AT_KV0 + (kc & 1) * AT_BUFS;

        // ---- S += Q K^T (3-term bf16 split)
#pragma unroll
        for (int ks = 0; ks < 4; ks++) {
#pragma unroll
            for (int p = 0; p < 4; p++) {
                uint32_t kh[4], kl[4];
                uint32_t off = SW128((uint32_t)((p * 16 + bn_row) * 128 +
                                                (ks * 16 + bn_kc0) * 2));
                LDSM_X4(kh, tb + 0 * 8192 + off);
                mma16816(s[2 * p + 0], qh[ks], &kh[0]);
                mma16816(s[2 * p + 1], qh[ks], &kh[2]);
                mma16816(s[2 * p + 0], ql[ks], &kh[0]);
                mma16816(s[2 * p + 1], ql[ks], &kh[2]);
                LDSM_X4(kl, tb + 1 * 8192 + off);
                mma16816(s[2 * p + 0], qh[ks], &kl[0]);
                mma16816(s[2 * p + 1], qh[ks], &kl[2]);
            }
        }

        // ---- online softmax (rows r=lane>>2 and r+8; quad shuffles)
        float mt0 = -1e30f, mt1 = -1e30f;
#pragma unroll
        for (int j = 0; j < 8; j++) {
            mt0 = fmaxf(mt0, fmaxf(s[j][0], s[j][1]));
            mt1 = fmaxf(mt1, fmaxf(s[j][2], s[j][3]));
        }
        mt0 = fmaxf(mt0, __shfl_xor_sync(0xffffffffu, mt0, 1));
        mt0 = fmaxf(mt0, __shfl_xor_sync(0xffffffffu, mt0, 2));
        mt1 = fmaxf(mt1, __shfl_xor_sync(0xffffffffu, mt1, 1));
        mt1 = fmaxf(mt1, __shfl_xor_sync(0xffffffffu, mt1, 2));

        float mn0 = fmaxf(m0r, mt0), mn1 = fmaxf(m1r, mt1);
        float al0 = __expf(m0r - mn0), al1 = __expf(m1r - mn1);
        m0r = mn0; m1r = mn1;

        float sum0 = 0.f, sum1 = 0.f;
#pragma unroll
        for (int j = 0; j < 8; j++) {
            s[j][0] = __expf(s[j][0] - mn0); s[j][1] = __expf(s[j][1] - mn0);
            s[j][2] = __expf(s[j][2] - mn1); s[j][3] = __expf(s[j][3] - mn1);
            sum0 += s[j][0] + s[j][1];
            sum1 += s[j][2] + s[j][3];
        }
        sum0 += __shfl_xor_sync(0xffffffffu, sum0, 1);
        sum0 += __shfl_xor_sync(0xffffffffu, sum0, 2);
        sum1 += __shfl_xor_sync(0xffffffffu, sum1, 1);
        sum1 += __shfl_xor_sync(0xffffffffu, sum1, 2);
        l0r = l0r * al0 + sum0;
        l1r = l1r * al1 + sum1;

#pragma unroll
        for (int j = 0; j < 8; j++) {
            o[j][0] *= al0; o[j][1] *= al0;
            o[j][2] *= al1; o[j][3] *= al1;
        }

        // ---- O += P V (3-term; pack P per-ks to keep registers low)
#pragma unroll
        for (int ks = 0; ks < 4; ks++) {
            uint32_t phi[4], plo[4];
#pragma unroll
            for (int half = 0; half < 2; half++) {
                const int j = 2 * ks + half;
                __nv_bfloat16 h0 = __float2bfloat16(s[j][0]);
                __nv_bfloat16 h1 = __float2bfloat16(s[j][1]);
                __nv_bfloat16 h2 = __float2bfloat16(s[j][2]);
                __nv_bfloat16 h3 = __float2bfloat16(s[j][3]);
                phi[2 * half + 0] = pack_bf162(h0, h1);
                phi[2 * half + 1] = pack_bf162(h2, h3);
                plo[2 * half + 0] = pack_bf162(
                    __float2bfloat16(s[j][0] - __bfloat162float(h0)),
                    __float2bfloat16(s[j][1] - __bfloat162float(h1)));
                plo[2 * half + 1] = pack_bf162(
                    __float2bfloat16(s[j][2] - __bfloat162float(h2)),
                    __float2bfloat16(s[j][3] - __bfloat162float(h3)));
            }
#pragma unroll
            for (int dp = 0; dp < 4; dp++) {
                uint32_t vh[4], vl[4];
                uint32_t off = SW128((uint32_t)((ks * 16 + vt_row) * 128 +
                                                (dp * 16 + vt_c0) * 2));
                LDSM_X4T(vh, tb + 2 * 8192 + off);
                mma16816(o[2 * dp + 0], phi, &vh[0]);
                mma16816(o[2 * dp + 1], phi, &vh[2]);
                mma16816(o[2 * dp + 0], plo, &vh[0]);
                mma16816(o[2 * dp + 1], plo, &vh[2]);
                LDSM_X4T(vl, tb + 3 * 8192 + off);
                mma16816(o[2 * dp + 0], phi, &vl[0]);
                mma16816(o[2 * dp + 1], phi, &vl[2]);
            }
        }

        __syncthreads();
        if (kc + 2 < 16) issue_kv(kc + 2);
    }

    // ---- epilogue: o/l -> bf16 hi/lo
    const float inv0 = 1.f / l0r, inv1 = 1.f / l1r;
    const int row0 = q0 + wid * 16 + (lane >> 2);
#pragma unroll
    for (int j = 0; j < 8; j++) {
        const int col = h * 64 + 8 * j + 2 * (lane & 3);
        float e0 = o[j][0] * inv0, e1 = o[j][1] * inv0;
        float e2 = o[j][2] * inv1, e3 = o[j][3] * inv1;
        __nv_bfloat16 h0 = __float2bfloat16(e0), h1 = __float2bfloat16(e1);
        __nv_bfloat16 h2 = __float2bfloat16(e2), h3 = __float2bfloat16(e3);
        size_t off0 = (size_t)(b * N_ + row0) * C_ + col;
        size_t off1 = (size_t)(b * N_ + row0 + 8) * C_ + col;
        *(__nv_bfloat162*)(ohi + off0) = __halves2bfloat162(h0, h1);
        *(__nv_bfloat162*)(olo + off0) = __halves2bfloat162(
            __float2bfloat16(e0 - __bfloat162float(h0)),
            __float2bfloat16(e1 - __bfloat162float(h1)));
        *(__nv_bfloat162*)(ohi + off1) = __halves2bfloat162(h2, h3);
        *(__nv_bfloat162*)(olo + off1) = __halves2bfloat162(
            __float2bfloat16(e2 - __bfloat162float(h2)),
            __float2bfloat16(e3 - __bfloat162float(h3)));
    }
}

// ---------------------------------------------------------------------------
extern "C" void kernel_launch(void* const* d_in, const int* in_sizes, int n_in,
                              void* d_out, int out_size)
{
    const float* q_x   = (const float*)d_in[0];
    const float* bias  = (const float*)d_in[1];
    const float* Wq    = (const float*)d_in[2];
    const float* bq    = (const float*)d_in[3];
    const float* Wk    = (const float*)d_in[4];
    const float* Wv    = (const float*)d_in[5];
    const float* Wo    = (const float*)d_in[6];
    const float* bo    = (const float*)d_in[7];
    const float* Wg    = (const float*)d_in[8];
    const float* bg    = (const float*)d_in[9];
    const float* gbias = (const float*)d_in[10];
    float* out = (float*)d_out;

    float* pg;
    __nv_bfloat16 *ahi, *alo, *whi, *wlo;
    __nv_bfloat16 *qh, *ql, *kh, *kl, *vh, *vl, *oh, *ol;
    cudaGetSymbolAddress((void**)&pg, g_gate);
    cudaGetSymbolAddress((void**)&ahi, g_ahi);
    cudaGetSymbolAddress((void**)&alo, g_alo);
    cudaGetSymbolAddress((void**)&whi, g_whi);
    cudaGetSymbolAddress((void**)&wlo, g_wlo);
    cudaGetSymbolAddress((void**)&qh, g_qhi);
    cudaGetSymbolAddress((void**)&ql, g_qlo);
    cudaGetSymbolAddress((void**)&kh, g_khi);
    cudaGetSymbolAddress((void**)&kl, g_klo);
    cudaGetSymbolAddress((void**)&vh, g_vhi);
    cudaGetSymbolAddress((void**)&vl, g_vlo);
    cudaGetSymbolAddress((void**)&oh, g_ohi);
    cudaGetSymbolAddress((void**)&ol, g_olo);

    cudaFuncSetAttribute(mma_proj, cudaFuncAttributeMaxDynamicSharedMemorySize, PROJ_SMEM);
    cudaFuncSetAttribute(attn_mma, cudaFuncAttributeMaxDynamicSharedMemorySize, ATT_SMEM);

    const int WN = C_ * C_;

    // split activations + all 5 weights (2 launches)
    split_kernel<<<(M_ * C_) / 1024, 256>>>(q_x, ahi, alo, M_ * C_);
    WPtrs wp; wp.p[0] = Wq; wp.p[1] = Wk; wp.p[2] = Wv; wp.p[3] = Wg; wp.p[4] = Wo;
    split5_kernel<<<(5 * WN) / 1024, 256>>>(wp, whi, wlo);

    // fused q/k/v/gate projections (bf16 hi/lo outputs for q,k,v; fp32 gate)
    dim3 pgrid(M_ / 128, C_ / 128, 4);
    mma_proj<<<pgrid, 256, PROJ_SMEM>>>(ahi, alo, whi, wlo,
                                        bq, bg, gbias, bo, pg,
                                        qh, ql, kh, kl, vh, vl, pg, nullptr, 0);

    // tensor-core attention -> bf16 hi/lo output
    dim3 agrid(N_ / 128, B_ * H_);
    attn_mma<<<agrid, 256, ATT_SMEM>>>(qh, ql, kh, kl, vh, vl, bias, oh, ol);

    // final gated projection (fp32 out)
    dim3 fgrid(M_ / 128, C_ / 128, 1);
    mma_proj<<<fgrid, 256, PROJ_SMEM>>>(oh, ol, whi, wlo,
                                        bq, bg, gbias, bo, pg,
                                        nullptr, nullptr, nullptr, nullptr, nullptr, nullptr,
                                        nullptr, out, 1);
}

// round 17
// speedup vs baseline: 3.2589x; 1.0363x over previous
#include <cuda_runtime.h>
#include <cuda_bf16.h>
#include <math.h>
#include <cstdint>

#define B_ 4
#define H_ 8
#define N_ 1024
#define D_ 64
#define C_ 512
#define M_ 4096   // B_*N_

// ---------------- scratch (no allocation allowed) ----------------
__device__ float g_gate[M_ * C_];
__device__ __nv_bfloat16 g_ahi[M_ * C_];
__device__ __nv_bfloat16 g_alo[M_ * C_];
__device__ __nv_bfloat16 g_qhi[M_ * C_];
__device__ __nv_bfloat16 g_qlo[M_ * C_];
__device__ __nv_bfloat16 g_khi[M_ * C_];
__device__ __nv_bfloat16 g_klo[M_ * C_];
__device__ __nv_bfloat16 g_vhi[M_ * C_];
__device__ __nv_bfloat16 g_vlo[M_ * C_];
__device__ __nv_bfloat16 g_ohi[M_ * C_];
__device__ __nv_bfloat16 g_olo[M_ * C_];
__device__ __nv_bfloat16 g_whi[5 * C_ * C_];
__device__ __nv_bfloat16 g_wlo[5 * C_ * C_];

// ---------------- helpers (plain sm_103-safe PTX only) ----------------
__device__ __forceinline__ uint32_t smem_u32(const void* p) {
    uint32_t a;
    asm("{ .reg .u64 t; cvta.to.shared.u64 t, %1; cvt.u32.u64 %0, t; }"
        : "=r"(a) : "l"(p));
    return a;
}
#define SW128(o) ((o) ^ (((o) >> 3) & 0x70))
#define SW64(o)  ((o) ^ (((o) >> 3) & 0x30))

#define CP_ASYNC16(dst, src) \
    asm volatile("cp.async.cg.shared.global [%0], [%1], 16;" \
                 :: "r"(dst), "l"(src) : "memory")
#define CP_COMMIT() asm volatile("cp.async.commit_group;" ::: "memory")
#define CP_WAIT0()  asm volatile("cp.async.wait_group 0;" ::: "memory")
#define CP_WAIT1()  asm volatile("cp.async.wait_group 1;" ::: "memory")
#define CP_WAIT2()  asm volatile("cp.async.wait_group 2;" ::: "memory")

#define LDSM_X4(r, addr) \
    asm volatile("ldmatrix.sync.aligned.m8n8.x4.shared.b16 {%0,%1,%2,%3}, [%4];" \
                 : "=r"((r)[0]), "=r"((r)[1]), "=r"((r)[2]), "=r"((r)[3]) : "r"(addr))
#define LDSM_X4T(r, addr) \
    asm volatile("ldmatrix.sync.aligned.m8n8.x4.trans.shared.b16 {%0,%1,%2,%3}, [%4];" \
                 : "=r"((r)[0]), "=r"((r)[1]), "=r"((r)[2]), "=r"((r)[3]) : "r"(addr))

__device__ __forceinline__ void mma16816(float* d, const uint32_t* a, const uint32_t* b) {
    asm volatile(
        "mma.sync.aligned.m16n8k16.row.col.f32.bf16.bf16.f32 "
        "{%0,%1,%2,%3}, {%4,%5,%6,%7}, {%8,%9}, {%0,%1,%2,%3};"
        : "+f"(d[0]), "+f"(d[1]), "+f"(d[2]), "+f"(d[3])
        : "r"(a[0]), "r"(a[1]), "r"(a[2]), "r"(a[3]), "r"(b[0]), "r"(b[1]));
}

__device__ __forceinline__ uint32_t pack_bf162(__nv_bfloat16 a, __nv_bfloat16 b) {
    __nv_bfloat162 t = __halves2bfloat162(a, b);
    return *reinterpret_cast<uint32_t*>(&t);
}

// ---------------- fp32 -> (hi, lo) bf16 split ----------------
__global__ __launch_bounds__(256) void split_kernel(
    const float* __restrict__ x, __nv_bfloat16* __restrict__ hi,
    __nv_bfloat16* __restrict__ lo, int n)
{
    int i = (blockIdx.x * 256 + threadIdx.x) * 4;
    if (i >= n) return;
    float4 v = *(const float4*)(x + i);
    float a0 = v.x, a1 = v.y, a2 = v.z, a3 = v.w;
    __nv_bfloat16 h0 = __float2bfloat16(a0), h1 = __float2bfloat16(a1);
    __nv_bfloat16 h2 = __float2bfloat16(a2), h3 = __float2bfloat16(a3);
    __nv_bfloat16 l0 = __float2bfloat16(a0 - __bfloat162float(h0));
    __nv_bfloat16 l1 = __float2bfloat16(a1 - __bfloat162float(h1));
    __nv_bfloat16 l2 = __float2bfloat16(a2 - __bfloat162float(h2));
    __nv_bfloat16 l3 = __float2bfloat16(a3 - __bfloat162float(h3));
    ((__nv_bfloat162*)(hi + i))[0] = __halves2bfloat162(h0, h1);
    ((__nv_bfloat162*)(hi + i))[1] = __halves2bfloat162(h2, h3);
    ((__nv_bfloat162*)(lo + i))[0] = __halves2bfloat162(l0, l1);
    ((__nv_bfloat162*)(lo + i))[1] = __halves2bfloat162(l2, l3);
}

// one launch for all 5 weight matrices (they land contiguously in g_whi/g_wlo)
struct WPtrs { const float* p[5]; };
__global__ __launch_bounds__(256) void split5_kernel(
    WPtrs w, __nv_bfloat16* __restrict__ hi, __nv_bfloat16* __restrict__ lo)
{
    const int WN = C_ * C_;
    int i = (blockIdx.x * 256 + threadIdx.x) * 4;
    if (i >= 5 * WN) return;
    int region = i / WN;
    int off = i - region * WN;
    float4 v = *(const float4*)(w.p[region] + off);
    float a0 = v.x, a1 = v.y, a2 = v.z, a3 = v.w;
    __nv_bfloat16 h0 = __float2bfloat16(a0), h1 = __float2bfloat16(a1);
    __nv_bfloat16 h2 = __float2bfloat16(a2), h3 = __float2bfloat16(a3);
    __nv_bfloat16 l0 = __float2bfloat16(a0 - __bfloat162float(h0));
    __nv_bfloat16 l1 = __float2bfloat16(a1 - __bfloat162float(h1));
    __nv_bfloat16 l2 = __float2bfloat16(a2 - __bfloat162float(h2));
    __nv_bfloat16 l3 = __float2bfloat16(a3 - __bfloat162float(h3));
    ((__nv_bfloat162*)(hi + i))[0] = __halves2bfloat162(h0, h1);
    ((__nv_bfloat162*)(hi + i))[1] = __halves2bfloat162(h2, h3);
    ((__nv_bfloat162*)(lo + i))[0] = __halves2bfloat162(l0, l1);
    ((__nv_bfloat162*)(lo + i))[1] = __halves2bfloat162(l2, l3);
}

// ---------------- mma.sync projection GEMM ----------------
// Tile 128x128, K-chunk 32 (64-byte rows, SW64 swizzle), 3-stage cp.async
// pipeline, 96KB smem -> 2 CTAs/SM.
// z: 0=q (x+bq)*0.125 -> bf16 hi/lo ; 1=k -> hi/lo ; 2=v -> hi/lo ;
// 3=sigmoid(x+bg+gbias) -> fp32 gate ; 4=(x+bo)*gate -> fp32 out
#define TSP 8192                   // one tile: 128 rows x 64 bytes
#define PROJ_SMEM (12 * TSP)       // 3 stages x 4 tiles = 98304

__global__ __launch_bounds__(256, 2) void mma_proj(
    const __nv_bfloat16* __restrict__ Ahi, const __nv_bfloat16* __restrict__ Alo,
    const __nv_bfloat16* __restrict__ Whi_base, const __nv_bfloat16* __restrict__ Wlo_base,
    const float* __restrict__ bq, const float* __restrict__ bg,
    const float* __restrict__ gbias, const float* __restrict__ bo,
    const float* __restrict__ gate,
    __nv_bfloat16* __restrict__ qhi, __nv_bfloat16* __restrict__ qlo,
    __nv_bfloat16* __restrict__ khi, __nv_bfloat16* __restrict__ klo,
    __nv_bfloat16* __restrict__ vhi, __nv_bfloat16* __restrict__ vlo,
    float* __restrict__ gatef, float* __restrict__ outo,
    int final_pass)
{
    extern __shared__ char smem[];
    const uint32_t sb = smem_u32(smem);
    const int tid = threadIdx.x;
    const int lane = tid & 31;
    const int wid = tid >> 5;
    const int wm = wid & 3;
    const int wn = wid >> 2;
    const int m0 = blockIdx.x * 128;
    const int o0 = blockIdx.y * 128;
    const int z = final_pass ? 4 : (int)blockIdx.z;

    const __nv_bfloat16* Whi = Whi_base + (size_t)z * C_ * C_;
    const __nv_bfloat16* Wlo = Wlo_base + (size_t)z * C_ * C_;

    float acc[2][8][4];
#pragma unroll
    for (int i = 0; i < 2; i++)
#pragma unroll
        for (int j = 0; j < 8; j++)
#pragma unroll
            for (int c = 0; c < 4; c++) acc[i][j][c] = 0.f;

    auto issue = [&](int ic) {
        const int buf = ic % 3;
        const uint32_t db = sb + buf * 4 * TSP;
        const int k0 = ic * 32;
#pragma unroll
        for (int it = 0; it < 2; it++) {
            int seg = it * 256 + tid;    // 0..511
            int r = seg >> 2;            // 0..127
            int c16 = seg & 3;           // 0..3
            uint32_t sw = SW64((uint32_t)(r * 64 + c16 * 16));
            size_t aoff = (size_t)(m0 + r) * C_ + k0 + c16 * 8;
            size_t woff = (size_t)(o0 + r) * C_ + k0 + c16 * 8;
            CP_ASYNC16(db + 0 * TSP + sw, Ahi + aoff);
            CP_ASYNC16(db + 1 * TSP + sw, Alo + aoff);
            CP_ASYNC16(db + 2 * TSP + sw, Whi + woff);
            CP_ASYNC16(db + 3 * TSP + sw, Wlo + woff);
        }
        CP_COMMIT();
    };

    const int a_row = wm * 32 + (lane & 15);
    const int a_kc0 = (lane >> 4) * 8;
    const int b_n   = wn * 64 + (lane & 7) + (lane >> 4) * 8;
    const int b_kc0 = ((lane >> 3) & 1) * 8;

    auto compute = [&](int buf) {
        const uint32_t tb = sb + buf * 4 * TSP;
#pragma unroll
        for (int ks = 0; ks < 2; ks++) {
            uint32_t ah[2][4], al[2][4], bf[4][4];
            const int akc = ks * 16 + a_kc0;
            const int bkc = ks * 16 + b_kc0;
#pragma unroll
            for (int mi = 0; mi < 2; mi++) {
                uint32_t off = (uint32_t)((a_row + mi * 16) * 64 + akc * 2);
                LDSM_X4(ah[mi], tb + 0 * TSP + SW64(off));
                LDSM_X4(al[mi], tb + 1 * TSP + SW64(off));
            }
#pragma unroll
            for (int p = 0; p < 4; p++) {
                uint32_t off = (uint32_t)((b_n + p * 16) * 64 + bkc * 2);
                LDSM_X4(bf[p], tb + 2 * TSP + SW64(off));
            }
#pragma unroll
            for (int mi = 0; mi < 2; mi++)
#pragma unroll
                for (int p = 0; p < 4; p++) {
                    mma16816(acc[mi][2 * p + 0], ah[mi], &bf[p][0]);
                    mma16816(acc[mi][2 * p + 1], ah[mi], &bf[p][2]);
                    mma16816(acc[mi][2 * p + 0], al[mi], &bf[p][0]);
                    mma16816(acc[mi][2 * p + 1], al[mi], &bf[p][2]);
                }
#pragma unroll
            for (int p = 0; p < 4; p++) {
                uint32_t off = (uint32_t)((b_n + p * 16) * 64 + bkc * 2);
                LDSM_X4(bf[p], tb + 3 * TSP + SW64(off));
            }
#pragma unroll
            for (int mi = 0; mi < 2; mi++)
#pragma unroll
                for (int p = 0; p < 4; p++) {
                    mma16816(acc[mi][2 * p + 0], ah[mi], &bf[p][0]);
                    mma16816(acc[mi][2 * p + 1], ah[mi], &bf[p][2]);
                }
        }
    };

    issue(0); issue(1); issue(2);
    for (int ic = 0; ic < 16; ic++) {
        if (ic < 14)      { CP_WAIT2(); }
        else if (ic == 14){ CP_WAIT1(); }
        else              { CP_WAIT0(); }
        __syncthreads();
        compute(ic % 3);
        __syncthreads();
        if (ic + 3 < 16) issue(ic + 3);
    }

    // ---- epilogue ----
    auto emit = [&](int m, int c, float v0, float v1) {
        if (z <= 2) {
            if (z == 0) { v0 = (v0 + bq[c]) * 0.125f; v1 = (v1 + bq[c + 1]) * 0.125f; }
            __nv_bfloat16 h0 = __float2bfloat16(v0), h1 = __float2bfloat16(v1);
            __nv_bfloat16 l0 = __float2bfloat16(v0 - __bfloat162float(h0));
            __nv_bfloat16 l1 = __float2bfloat16(v1 - __bfloat162float(h1));
            __nv_bfloat16* oh = (z == 0) ? qhi : (z == 1) ? khi : vhi;
            __nv_bfloat16* ol = (z == 0) ? qlo : (z == 1) ? klo : vlo;
            *(__nv_bfloat162*)(oh + (size_t)m * C_ + c) = __halves2bfloat162(h0, h1);
            *(__nv_bfloat162*)(ol + (size_t)m * C_ + c) = __halves2bfloat162(l0, l1);
        } else if (z == 3) {
            v0 = 1.f / (1.f + __expf(-(v0 + bg[c] + gbias[c])));
            v1 = 1.f / (1.f + __expf(-(v1 + bg[c + 1] + gbias[c + 1])));
            *(float2*)(gatef + (size_t)m * C_ + c) = make_float2(v0, v1);
        } else {
            v0 = (v0 + bo[c]) * gate[(size_t)m * C_ + c];
            v1 = (v1 + bo[c + 1]) * gate[(size_t)m * C_ + c + 1];
            *(float2*)(outo + (size_t)m * C_ + c) = make_float2(v0, v1);
        }
    };

#pragma unroll
    for (int mi = 0; mi < 2; mi++)
#pragma unroll
        for (int nj = 0; nj < 8; nj++) {
            int row = m0 + wm * 32 + mi * 16 + (lane >> 2);
            int col = o0 + wn * 64 + nj * 8 + (lane & 3) * 2;
            emit(row,     col, acc[mi][nj][0], acc[mi][nj][1]);
            emit(row + 8, col, acc[mi][nj][2], acc[mi][nj][3]);
        }
}

// ---------------- tensor-core flash attention with bias ----------------
// grid (N_/128, B_*H_); 256 threads; warp w owns query rows [w*16, w*16+16).
// smem: Qhi 16K, Qlo 16K, then 2 KV buffers of {Khi,Klo,Vhi,Vlo} 8K each.
// Bias is loaded directly into the S accumulators (mma d = a*b + d).
#define AT_KV0 32768
#define AT_BUFS 32768
#define ATT_SMEM (AT_KV0 + 2 * AT_BUFS)   // 98304

__global__ __launch_bounds__(256, 2) void attn_mma(
    const __nv_bfloat16* __restrict__ qhi, const __nv_bfloat16* __restrict__ qlo,
    const __nv_bfloat16* __restrict__ khi, const __nv_bfloat16* __restrict__ klo,
    const __nv_bfloat16* __restrict__ vhi, const __nv_bfloat16* __restrict__ vlo,
    const float* __restrict__ bias,
    __nv_bfloat16* __restrict__ ohi, __nv_bfloat16* __restrict__ olo)
{
    extern __shared__ char smem[];
    const uint32_t sb = smem_u32(smem);
    const int tid = threadIdx.x;
    const int lane = tid & 31;
    const int wid = tid >> 5;           // 0..7 -> m offset wid*16
    const int qt = blockIdx.x;
    const int bh = blockIdx.y;
    const int b = bh >> 3, h = bh & 7;
    const int q0 = qt * 128;

    const size_t qbase  = (size_t)(b * N_ + q0) * C_ + h * 64;
    const size_t kvbase = (size_t)(b * N_) * C_ + h * 64;
    const float* biasb = bias + (size_t)bh * N_ * N_;

    // ---- prologue: load Q tiles + KV chunk 0 (group 0), KV chunk 1 (group 1)
    {
#pragma unroll
        for (int it = 0; it < 4; it++) {
            int seg = it * 256 + tid;       // 0..1023
            int r = seg >> 3;               // 0..127
            int c16 = seg & 7;
            uint32_t sw = SW128((uint32_t)(r * 128 + c16 * 16));
            size_t off = qbase + (size_t)r * C_ + c16 * 8;
            CP_ASYNC16(sb + sw, qhi + off);
            CP_ASYNC16(sb + 16384 + sw, qlo + off);
        }
    }
    auto issue_kv = [&](int kc) {
        const uint32_t db = sb + AT_KV0 + (kc & 1) * AT_BUFS;
#pragma unroll
        for (int it = 0; it < 2; it++) {
            int seg = it * 256 + tid;       // 0..511
            int r = seg >> 3;               // 0..63
            int c16 = seg & 7;
            uint32_t sw = SW128((uint32_t)(r * 128 + c16 * 16));
            size_t off = kvbase + (size_t)(kc * 64 + r) * C_ + c16 * 8;
            CP_ASYNC16(db + 0 * 8192 + sw, khi + off);
            CP_ASYNC16(db + 1 * 8192 + sw, klo + off);
            CP_ASYNC16(db + 2 * 8192 + sw, vhi + off);
            CP_ASYNC16(db + 3 * 8192 + sw, vlo + off);
        }
        CP_COMMIT();
    };
    issue_kv(0);   // group 0 (with Q)
    issue_kv(1);   // group 1

    uint32_t qh[4][4], ql[4][4];

    float o[8][4];
    float m0r = -1e30f, m1r = -1e30f, l0r = 0.f, l1r = 0.f;
#pragma unroll
    for (int j = 0; j < 8; j++)
#pragma unroll
        for (int c = 0; c < 4; c++) o[j][c] = 0.f;

    const int a_row = wid * 16 + (lane & 15);
    const int a_kc0 = (lane >> 4) * 8;
    const int bn_row = (lane & 7) + (lane >> 4) * 8;
    const int bn_kc0 = ((lane >> 3) & 1) * 8;
    const int vt_row = (lane & 15);
    const int vt_c0  = (lane >> 4) * 8;

    // bias row pointers for this thread (rows r, r+8 of the C-fragment)
    const int r0g = q0 + wid * 16 + (lane >> 2);
    const float* bp0 = biasb + (size_t)r0g * N_ + 2 * (lane & 3);
    const float* bp1 = bp0 + (size_t)8 * N_;

    bool qloaded = false;

    for (int kc = 0; kc < 16; kc++) {
        // ---- S init = bias (mma accumulates q.k on top)
        float s[8][4];
        {
            const float* b0 = bp0 + kc * 64;
            const float* b1 = bp1 + kc * 64;
#pragma unroll
            for (int j = 0; j < 8; j++) {
                float2 t0 = *(const float2*)(b0 + 8 * j);
                float2 t1 = *(const float2*)(b1 + 8 * j);
                s[j][0] = t0.x; s[j][1] = t0.y; s[j][2] = t1.x; s[j][3] = t1.y;
            }
        }

        if (kc < 15) { CP_WAIT1(); } else { CP_WAIT0(); }
        __syncthreads();

        if (!qloaded) {
            qloaded = true;
#pragma unroll
            for (int ks = 0; ks < 4; ks++) {
                uint32_t off = SW128((uint32_t)(a_row * 128 + (ks * 16 + a_kc0) * 2));
                LDSM_X4(qh[ks], sb + off);
                LDSM_X4(ql[ks], sb + 16384 + off);
            }
        }

        const uint32_t tb = sb + AT_KV0 + (kc & 1) * AT_BUFS;

        // ---- S += Q K^T (3-term bf16 split)
#pragma unroll
        for (int ks = 0; ks < 4; ks++) {
#pragma unroll
            for (int p = 0; p < 4; p++) {
                uint32_t kh[4], kl[4];
                uint32_t off = SW128((uint32_t)((p * 16 + bn_row) * 128 +
                                                (ks * 16 + bn_kc0) * 2));
                LDSM_X4(kh, tb + 0 * 8192 + off);
                mma16816(s[2 * p + 0], qh[ks], &kh[0]);
                mma16816(s[2 * p + 1], qh[ks], &kh[2]);
                mma16816(s[2 * p + 0], ql[ks], &kh[0]);
                mma16816(s[2 * p + 1], ql[ks], &kh[2]);
                LDSM_X4(kl, tb + 1 * 8192 + off);
                mma16816(s[2 * p + 0], qh[ks], &kl[0]);
                mma16816(s[2 * p + 1], qh[ks], &kl[2]);
            }
        }

        // ---- online softmax (rows r=lane>>2 and r+8; quad shuffles)
        float mt0 = -1e30f, mt1 = -1e30f;
#pragma unroll
        for (int j = 0; j < 8; j++) {
            mt0 = fmaxf(mt0, fmaxf(s[j][0], s[j][1]));
            mt1 = fmaxf(mt1, fmaxf(s[j][2], s[j][3]));
        }
        mt0 = fmaxf(mt0, __shfl_xor_sync(0xffffffffu, mt0, 1));
        mt0 = fmaxf(mt0, __shfl_xor_sync(0xffffffffu, mt0, 2));
        mt1 = fmaxf(mt1, __shfl_xor_sync(0xffffffffu, mt1, 1));
        mt1 = fmaxf(mt1, __shfl_xor_sync(0xffffffffu, mt1, 2));

        float mn0 = fmaxf(m0r, mt0), mn1 = fmaxf(m1r, mt1);
        float al0 = __expf(m0r - mn0), al1 = __expf(m1r - mn1);
        m0r = mn0; m1r = mn1;

        float sum0 = 0.f, sum1 = 0.f;
#pragma unroll
        for (int j = 0; j < 8; j++) {
            s[j][0] = __expf(s[j][0] - mn0); s[j][1] = __expf(s[j][1] - mn0);
            s[j][2] = __expf(s[j][2] - mn1); s[j][3] = __expf(s[j][3] - mn1);
            sum0 += s[j][0] + s[j][1];
            sum1 += s[j][2] + s[j][3];
        }
        sum0 += __shfl_xor_sync(0xffffffffu, sum0, 1);
        sum0 += __shfl_xor_sync(0xffffffffu, sum0, 2);
        sum1 += __shfl_xor_sync(0xffffffffu, sum1, 1);
        sum1 += __shfl_xor_sync(0xffffffffu, sum1, 2);
        l0r = l0r * al0 + sum0;
        l1r = l1r * al1 + sum1;

#pragma unroll
        for (int j = 0; j < 8; j++) {
            o[j][0] *= al0; o[j][1] *= al0;
            o[j][2] *= al1; o[j][3] *= al1;
        }

        // ---- O += P V (3-term; pack P per-ks to keep registers low)
#pragma unroll
        for (int ks = 0; ks < 4; ks++) {
            uint32_t phi[4], plo[4];
#pragma unroll
            for (int half = 0; half < 2; half++) {
                const int j = 2 * ks + half;
                __nv_bfloat16 h0 = __float2bfloat16(s[j][0]);
                __nv_bfloat16 h1 = __float2bfloat16(s[j][1]);
                __nv_bfloat16 h2 = __float2bfloat16(s[j][2]);
                __nv_bfloat16 h3 = __float2bfloat16(s[j][3]);
                phi[2 * half + 0] = pack_bf162(h0, h1);
                phi[2 * half + 1] = pack_bf162(h2, h3);
                plo[2 * half + 0] = pack_bf162(
                    __float2bfloat16(s[j][0] - __bfloat162float(h0)),
                    __float2bfloat16(s[j][1] - __bfloat162float(h1)));
                plo[2 * half + 1] = pack_bf162(
                    __float2bfloat16(s[j][2] - __bfloat162float(h2)),
                    __float2bfloat16(s[j][3] - __bfloat162float(h3)));
            }
#pragma unroll
            for (int dp = 0; dp < 4; dp++) {
                uint32_t vh[4], vl[4];
                uint32_t off = SW128((uint32_t)((ks * 16 + vt_row) * 128 +
                                                (dp * 16 + vt_c0) * 2));
                LDSM_X4T(vh, tb + 2 * 8192 + off);
                mma16816(o[2 * dp + 0], phi, &vh[0]);
                mma16816(o[2 * dp + 1], phi, &vh[2]);
                mma16816(o[2 * dp + 0], plo, &vh[0]);
                mma16816(o[2 * dp + 1], plo, &vh[2]);
                LDSM_X4T(vl, tb + 3 * 8192 + off);
                mma16816(o[2 * dp + 0], phi, &vl[0]);
                mma16816(o[2 * dp + 1], phi, &vl[2]);
            }
        }

        __syncthreads();
        if (kc + 2 < 16) issue_kv(kc + 2);
    }

    // ---- epilogue: o/l -> bf16 hi/lo
    const float inv0 = 1.f / l0r, inv1 = 1.f / l1r;
    const int row0 = q0 + wid * 16 + (lane >> 2);
#pragma unroll
    for (int j = 0; j < 8; j++) {
        const int col = h * 64 + 8 * j + 2 * (lane & 3);
        float e0 = o[j][0] * inv0, e1 = o[j][1] * inv0;
        float e2 = o[j][2] * inv1, e3 = o[j][3] * inv1;
        __nv_bfloat16 h0 = __float2bfloat16(e0), h1 = __float2bfloat16(e1);
        __nv_bfloat16 h2 = __float2bfloat16(e2), h3 = __float2bfloat16(e3);
        size_t off0 = (size_t)(b * N_ + row0) * C_ + col;
        size_t off1 = (size_t)(b * N_ + row0 + 8) * C_ + col;
        *(__nv_bfloat162*)(ohi + off0) = __halves2bfloat162(h0, h1);
        *(__nv_bfloat162*)(olo + off0) = __halves2bfloat162(
            __float2bfloat16(e0 - __bfloat162float(h0)),
            __float2bfloat16(e1 - __bfloat162float(h1)));
        *(__nv_bfloat162*)(ohi + off1) = __halves2bfloat162(h2, h3);
        *(__nv_bfloat162*)(olo + off1) = __halves2bfloat162(
            __float2bfloat16(e2 - __bfloat162float(h2)),
            __float2bfloat16(e3 - __bfloat162float(h3)));
    }
}

// ---------------------------------------------------------------------------
extern "C" void kernel_launch(void* const* d_in, const int* in_sizes, int n_in,
                              void* d_out, int out_size)
{
    const float* q_x   = (const float*)d_in[0];
    const float* bias  = (const float*)d_in[1];
    const float* Wq    = (const float*)d_in[2];
    const float* bq    = (const float*)d_in[3];
    const float* Wk    = (const float*)d_in[4];
    const float* Wv    = (const float*)d_in[5];
    const float* Wo    = (const float*)d_in[6];
    const float* bo    = (const float*)d_in[7];
    const float* Wg    = (const float*)d_in[8];
    const float* bg    = (const float*)d_in[9];
    const float* gbias = (const float*)d_in[10];
    float* out = (float*)d_out;

    float* pg;
    __nv_bfloat16 *ahi, *alo, *whi, *wlo;
    __nv_bfloat16 *qh, *ql, *kh, *kl, *vh, *vl, *oh, *ol;
    cudaGetSymbolAddress((void**)&pg, g_gate);
    cudaGetSymbolAddress((void**)&ahi, g_ahi);
    cudaGetSymbolAddress((void**)&alo, g_alo);
    cudaGetSymbolAddress((void**)&whi, g_whi);
    cudaGetSymbolAddress((void**)&wlo, g_wlo);
    cudaGetSymbolAddress((void**)&qh, g_qhi);
    cudaGetSymbolAddress((void**)&ql, g_qlo);
    cudaGetSymbolAddress((void**)&kh, g_khi);
    cudaGetSymbolAddress((void**)&kl, g_klo);
    cudaGetSymbolAddress((void**)&vh, g_vhi);
    cudaGetSymbolAddress((void**)&vl, g_vlo);
    cudaGetSymbolAddress((void**)&oh, g_ohi);
    cudaGetSymbolAddress((void**)&ol, g_olo);

    cudaFuncSetAttribute(mma_proj, cudaFuncAttributeMaxDynamicSharedMemorySize, PROJ_SMEM);
    cudaFuncSetAttribute(attn_mma, cudaFuncAttributeMaxDynamicSharedMemorySize, ATT_SMEM);

    const int WN = C_ * C_;

    // split activations + all 5 weights (2 launches)
    split_kernel<<<(M_ * C_) / 1024, 256>>>(q_x, ahi, alo, M_ * C_);
    WPtrs wp; wp.p[0] = Wq; wp.p[1] = Wk; wp.p[2] = Wv; wp.p[3] = Wg; wp.p[4] = Wo;
    split5_kernel<<<(5 * WN) / 1024, 256>>>(wp, whi, wlo);

    // fused q/k/v/gate projections (bf16 hi/lo outputs for q,k,v; fp32 gate)
    dim3 pgrid(M_ / 128, C_ / 128, 4);
    mma_proj<<<pgrid, 256, PROJ_SMEM>>>(ahi, alo, whi, wlo,
                                        bq, bg, gbias, bo, pg,
                                        qh, ql, kh, kl, vh, vl, pg, nullptr, 0);

    // tensor-core attention -> bf16 hi/lo output
    dim3 agrid(N_ / 128, B_ * H_);
    attn_mma<<<agrid, 256, ATT_SMEM>>>(qh, ql, kh, kl, vh, vl, bias, oh, ol);

    // final gated projection (fp32 out)
    dim3 fgrid(M_ / 128, C_ / 128, 1);
    mma_proj<<<fgrid, 256, PROJ_SMEM>>>(oh, ol, whi, wlo,
                                        bq, bg, gbias, bo, pg,
                                        nullptr, nullptr, nullptr, nullptr, nullptr, nullptr,
                                        nullptr, out, 1);
}